// round 1
// baseline (speedup 1.0000x reference)
#include <cuda_runtime.h>
#include <cuda_bf16.h>
#include <cstddef>

// ---------------- problem constants ----------------
#define TT      64
#define MM      64
#define NROWS   4096      // T*M
#define ROI     2048
#define SPA     4
#define WORD    300
#define ROISPA  2052      // ROI+SPA
#define INW     2352      // ROI+SPA+WORD
#define HH      512
#define DD      256
#define RELIN   556       // D + WORD

// ---------------- scratch (device globals; no allocation) ----------------
__device__ float g_X   [NROWS * ROISPA];   // packed [roi|spatial]
__device__ float g_Y1  [NROWS * HH];
__device__ float g_Y2  [NROWS * HH];
__device__ float g_A   [NROWS * HH];
__device__ float g_B   [NROWS * HH];

__device__ float g_Wsum_s[HH * DD], g_Wsum_o[HH * DD];
__device__ float g_Wc_s  [HH * DD], g_Wc_o  [HH * DD];
__device__ float g_Wf_s  [HH * HH], g_Wf_o  [HH * HH];
__device__ float g_Wcc_s [HH * HH], g_Wcc_o [HH * HH];

__device__ float g_c_subj[HH], g_c_obj[HH], g_bias512[HH];
__device__ float g_bf_s[HH], g_bf_o[HH], g_cvec_s[HH], g_cvec_o[HH];

// ---------------- pack X = [roi | spatial] ----------------
__global__ void pack_x_kernel(const float* __restrict__ roi,
                              const float* __restrict__ spa) {
    int r = blockIdx.x;                 // 0..4095
    for (int k = threadIdx.x; k < ROISPA; k += blockDim.x) {
        float v = (k < ROI) ? roi[(size_t)r * ROI + k]
                            : spa[(size_t)r * SPA + (k - ROI)];
        g_X[(size_t)r * ROISPA + k] = v;
    }
}

// ---------------- precompute constant biases + Wsum ----------------
__global__ void pre_vec_kernel(const float* __restrict__ subj_w1, const float* __restrict__ subj_b1,
                               const float* __restrict__ obj_w1,  const float* __restrict__ obj_b1,
                               const float* __restrict__ rel_w1,  const float* __restrict__ rel_b1,
                               const float* __restrict__ subj_emb, const float* __restrict__ obj_emb,
                               const float* __restrict__ pred_emb,
                               const float* __restrict__ fuse_s_w1, const float* __restrict__ fuse_o_w1) {
    int h = blockIdx.x;          // 0..511
    int t = threadIdx.x;         // 128 threads
    float s1 = 0.f, s2 = 0.f, s3 = 0.f;
    for (int w = t; w < WORD; w += 128) {
        s1 += subj_w1[(size_t)h * INW + ROISPA + w] * subj_emb[w];
        s2 += obj_w1 [(size_t)h * INW + ROISPA + w] * obj_emb[w];
        s3 += rel_w1 [(size_t)h * RELIN + DD + w]   * pred_emb[w];
    }
    for (int o = 16; o > 0; o >>= 1) {
        s1 += __shfl_down_sync(0xffffffffu, s1, o);
        s2 += __shfl_down_sync(0xffffffffu, s2, o);
        s3 += __shfl_down_sync(0xffffffffu, s3, o);
    }
    __shared__ float red[3][4];
    int wrp = t >> 5, lan = t & 31;
    if (lan == 0) { red[0][wrp] = s1; red[1][wrp] = s2; red[2][wrp] = s3; }
    __syncthreads();
    if (t == 0) {
        g_c_subj[h]  = red[0][0] + red[0][1] + red[0][2] + red[0][3] + subj_b1[h];
        g_c_obj[h]   = red[1][0] + red[1][1] + red[1][2] + red[1][3] + obj_b1[h];
        g_bias512[h] = red[2][0] + red[2][1] + red[2][2] + red[2][3] + rel_b1[h];
    }
    for (int d = t; d < DD; d += 128) {
        g_Wsum_s[h * DD + d] = fuse_s_w1[(size_t)h * (2*DD) + d] + fuse_s_w1[(size_t)h * (2*DD) + DD + d];
        g_Wsum_o[h * DD + d] = fuse_o_w1[(size_t)h * (2*DD) + d] + fuse_o_w1[(size_t)h * (2*DD) + DD + d];
    }
}

// ---------------- Wc[h,d] = sum_k rel_w1[h,k] * Wr[k,d]  (k<256) ----------------
__global__ void pre_wc_kernel(const float* __restrict__ rel_w1,
                              const float* __restrict__ W_rs,
                              const float* __restrict__ W_ro) {
    int h  = blockIdx.x;   // 0..511
    int br = blockIdx.y;   // 0 subj, 1 obj
    int d  = threadIdx.x;  // 256
    const float* Wr = br ? W_ro : W_rs;
    float* out = br ? g_Wc_o : g_Wc_s;
    __shared__ float wd[DD];
    wd[d] = rel_w1[(size_t)h * RELIN + d];
    __syncthreads();
    float acc = 0.f;
    #pragma unroll 4
    for (int k = 0; k < DD; k++) acc = fmaf(wd[k], Wr[(size_t)k * DD + d], acc);
    out[h * DD + d] = acc;
}

// ---------------- Wf[h2,h] = sum_d Wsum[h2,d]*w2[d,h]; bf[h2]=sum_d Wsum*b2 + b1f ----------------
__global__ void pre_wf_kernel(const float* __restrict__ subj_w2, const float* __restrict__ subj_b2,
                              const float* __restrict__ fuse_s_b1,
                              const float* __restrict__ obj_w2,  const float* __restrict__ obj_b2,
                              const float* __restrict__ fuse_o_b1) {
    int h2 = blockIdx.x;   // 0..511
    int br = blockIdx.y;
    int t  = threadIdx.x;  // 512
    const float* Wsum = br ? g_Wsum_o : g_Wsum_s;
    const float* w2   = br ? obj_w2   : subj_w2;
    const float* b2   = br ? obj_b2   : subj_b2;
    const float* b1f  = br ? fuse_o_b1 : fuse_s_b1;
    float* Wf = br ? g_Wf_o : g_Wf_s;
    float* bf = br ? g_bf_o : g_bf_s;
    __shared__ float ws[DD];
    if (t < DD) ws[t] = Wsum[h2 * DD + t];
    __syncthreads();
    float acc = 0.f;
    #pragma unroll 4
    for (int d = 0; d < DD; d++) acc = fmaf(ws[d], w2[(size_t)d * HH + t], acc);
    Wf[(size_t)h2 * HH + t] = acc;
    if (t == 0) {
        float b = 0.f;
        for (int d = 0; d < DD; d++) b += ws[d] * b2[d];
        bf[h2] = b + b1f[h2];
    }
}

// ---------------- Wcc[h,h2] = sum_d Wc[h,d]*fw2[d,h2]; cvec[h]=sum_d Wc*fb2 ----------------
__global__ void pre_wcc_kernel(const float* __restrict__ fuse_s_w2, const float* __restrict__ fuse_s_b2,
                               const float* __restrict__ fuse_o_w2, const float* __restrict__ fuse_o_b2) {
    int h  = blockIdx.x;
    int br = blockIdx.y;
    int t  = threadIdx.x;  // 512
    const float* Wc  = br ? g_Wc_o : g_Wc_s;
    const float* fw2 = br ? fuse_o_w2 : fuse_s_w2;
    const float* fb2 = br ? fuse_o_b2 : fuse_s_b2;
    float* Wcc  = br ? g_Wcc_o : g_Wcc_s;
    float* cvec = br ? g_cvec_o : g_cvec_s;
    __shared__ float ws[DD];
    if (t < DD) ws[t] = Wc[h * DD + t];
    __syncthreads();
    float acc = 0.f;
    #pragma unroll 4
    for (int d = 0; d < DD; d++) acc = fmaf(ws[d], fw2[(size_t)d * HH + t], acc);
    Wcc[(size_t)h * HH + t] = acc;
    if (t == 0) {
        float b = 0.f;
        for (int d = 0; d < DD; d++) b += ws[d] * fb2[d];
        cvec[h] = b;
    }
}

// ---------------- generic NT GEMM: C[m,n] = act(sum_k X[m,k]*W[n,k] + bias[n]) ----------------
// BM=BN=128, BK=16, 256 threads, 8x8 microtile. M,N multiples of 128; K multiple of 4.
template<bool RELU>
__global__ __launch_bounds__(256, 2)
void gemm128_kernel(const float* __restrict__ X, int ldx,
                    const float* __restrict__ W, int ldw,
                    const float* __restrict__ bias,
                    float* __restrict__ C, int N, int K) {
    __shared__ float Xs[16][132];
    __shared__ float Ws[16][132];
    const int m0 = blockIdx.y * 128;
    const int n0 = blockIdx.x * 128;
    const int tid = threadIdx.x;
    const int tr = tid >> 4, tc = tid & 15;

    float acc[8][8];
    #pragma unroll
    for (int i = 0; i < 8; i++)
        #pragma unroll
        for (int j = 0; j < 8; j++) acc[i][j] = 0.f;

    for (int k0 = 0; k0 < K; k0 += 16) {
        #pragma unroll
        for (int e = 0; e < 2; e++) {
            int idx = e * 256 + tid;          // 0..511
            int m = idx >> 2, kq = (idx & 3) * 4;
            float4 v = make_float4(0.f, 0.f, 0.f, 0.f);
            if (k0 + kq < K)
                v = *reinterpret_cast<const float4*>(&X[(size_t)(m0 + m) * ldx + k0 + kq]);
            Xs[kq + 0][m] = v.x; Xs[kq + 1][m] = v.y; Xs[kq + 2][m] = v.z; Xs[kq + 3][m] = v.w;
        }
        #pragma unroll
        for (int e = 0; e < 2; e++) {
            int idx = e * 256 + tid;
            int n = idx >> 2, kq = (idx & 3) * 4;
            float4 v = make_float4(0.f, 0.f, 0.f, 0.f);
            if (k0 + kq < K)
                v = *reinterpret_cast<const float4*>(&W[(size_t)(n0 + n) * ldw + k0 + kq]);
            Ws[kq + 0][n] = v.x; Ws[kq + 1][n] = v.y; Ws[kq + 2][n] = v.z; Ws[kq + 3][n] = v.w;
        }
        __syncthreads();
        #pragma unroll
        for (int kk = 0; kk < 16; kk++) {
            float4 a0 = *reinterpret_cast<const float4*>(&Xs[kk][tr * 8]);
            float4 a1 = *reinterpret_cast<const float4*>(&Xs[kk][tr * 8 + 4]);
            float4 b0 = *reinterpret_cast<const float4*>(&Ws[kk][tc * 8]);
            float4 b1 = *reinterpret_cast<const float4*>(&Ws[kk][tc * 8 + 4]);
            float a[8] = {a0.x, a0.y, a0.z, a0.w, a1.x, a1.y, a1.z, a1.w};
            float b[8] = {b0.x, b0.y, b0.z, b0.w, b1.x, b1.y, b1.z, b1.w};
            #pragma unroll
            for (int i = 0; i < 8; i++)
                #pragma unroll
                for (int j = 0; j < 8; j++)
                    acc[i][j] = fmaf(a[i], b[j], acc[i][j]);
        }
        __syncthreads();
    }

    float bv[8];
    #pragma unroll
    for (int j = 0; j < 8; j++) bv[j] = bias[n0 + tc * 8 + j];
    #pragma unroll
    for (int i = 0; i < 8; i++) {
        int m = m0 + tr * 8 + i;
        float r[8];
        #pragma unroll
        for (int j = 0; j < 8; j++) {
            float v = acc[i][j] + bv[j];
            r[j] = RELU ? fmaxf(v, 0.f) : v;
        }
        float4* cp = reinterpret_cast<float4*>(&C[(size_t)m * N + n0 + tc * 8]);
        cp[0] = make_float4(r[0], r[1], r[2], r[3]);
        cp[1] = make_float4(r[4], r[5], r[6], r[7]);
    }
}

// ---------------- final pairwise GEMM ----------------
// out[t,i,j,n] = sum_k relu(A[t*64+i,k] - B[t*64+j,k] + bias512[k]) * W2[n,k] + b2[n]
// grid (2, 32, 64); block tile = 128 pairs (2 i's x 64 j's) x 128 n; 256 threads, 8x8 micro.
__global__ __launch_bounds__(256, 2)
void final_kernel(const float* __restrict__ W2,
                  const float* __restrict__ b2,
                  float* __restrict__ out) {
    __shared__ float Hs [16][132];
    __shared__ float W2s[16][132];
    __shared__ float Bs [64][17];
    __shared__ float As [2][17];
    __shared__ float biasS[16];

    const int t     = blockIdx.z;
    const int ibase = blockIdx.y * 2;
    const int n0    = blockIdx.x * 128;
    const int tid   = threadIdx.x;
    const int tr = tid >> 4, tc = tid & 15;

    const float* Arow = g_A + (size_t)(t * 64 + ibase) * HH;
    const float* Brow = g_B + (size_t)(t * 64) * HH;

    float acc[8][8];
    #pragma unroll
    for (int i = 0; i < 8; i++)
        #pragma unroll
        for (int j = 0; j < 8; j++) acc[i][j] = 0.f;

    for (int k0 = 0; k0 < HH; k0 += 16) {
        if (tid < 32) As[tid >> 4][tid & 15] = Arow[(size_t)(tid >> 4) * HH + k0 + (tid & 15)];
        if (tid < 16) biasS[tid] = g_bias512[k0 + tid];
        {   // Bs: 64 x 16 = 256 float4, one per thread
            int j = tid >> 2, kq = (tid & 3) * 4;
            float4 v = *reinterpret_cast<const float4*>(&Brow[(size_t)j * HH + k0 + kq]);
            Bs[j][kq + 0] = v.x; Bs[j][kq + 1] = v.y; Bs[j][kq + 2] = v.z; Bs[j][kq + 3] = v.w;
        }
        #pragma unroll
        for (int e = 0; e < 2; e++) {   // W2s: 128 x 16
            int idx = e * 256 + tid;
            int n = idx >> 2, kq = (idx & 3) * 4;
            float4 v = *reinterpret_cast<const float4*>(&W2[(size_t)(n0 + n) * HH + k0 + kq]);
            W2s[kq + 0][n] = v.x; W2s[kq + 1][n] = v.y; W2s[kq + 2][n] = v.z; W2s[kq + 3][n] = v.w;
        }
        __syncthreads();
        #pragma unroll
        for (int e = 0; e < 8; e++) {   // build Hs: 16 x 128
            int idx = e * 256 + tid;
            int k = idx >> 7, p = idx & 127;
            float v = As[p >> 6][k] - Bs[p & 63][k] + biasS[k];
            Hs[k][p] = fmaxf(v, 0.f);
        }
        __syncthreads();
        #pragma unroll
        for (int kk = 0; kk < 16; kk++) {
            float4 a0 = *reinterpret_cast<const float4*>(&Hs[kk][tr * 8]);
            float4 a1 = *reinterpret_cast<const float4*>(&Hs[kk][tr * 8 + 4]);
            float4 b0 = *reinterpret_cast<const float4*>(&W2s[kk][tc * 8]);
            float4 b1 = *reinterpret_cast<const float4*>(&W2s[kk][tc * 8 + 4]);
            float a[8] = {a0.x, a0.y, a0.z, a0.w, a1.x, a1.y, a1.z, a1.w};
            float b[8] = {b0.x, b0.y, b0.z, b0.w, b1.x, b1.y, b1.z, b1.w};
            #pragma unroll
            for (int i = 0; i < 8; i++)
                #pragma unroll
                for (int j = 0; j < 8; j++)
                    acc[i][j] = fmaf(a[i], b[j], acc[i][j]);
        }
        __syncthreads();
    }

    float bv[8];
    #pragma unroll
    for (int j = 0; j < 8; j++) bv[j] = b2[n0 + tc * 8 + j];

    const int irow = ibase + (tr >> 3);
    const int jcol = (tr & 7) * 8;
    #pragma unroll
    for (int ii = 0; ii < 8; ii++) {
        int j = jcol + ii;
        size_t off = ((size_t)((t * 64 + irow) * 64 + j)) * 256 + n0 + tc * 8;
        float4* op = reinterpret_cast<float4*>(&out[off]);
        op[0] = make_float4(acc[ii][0] + bv[0], acc[ii][1] + bv[1],
                            acc[ii][2] + bv[2], acc[ii][3] + bv[3]);
        op[1] = make_float4(acc[ii][4] + bv[4], acc[ii][5] + bv[5],
                            acc[ii][6] + bv[6], acc[ii][7] + bv[7]);
    }
}

// ---------------- host launch ----------------
extern "C" void kernel_launch(void* const* d_in, const int* in_sizes, int n_in,
                              void* d_out, int out_size) {
    const float* roi       = (const float*)d_in[0];
    const float* spatial   = (const float*)d_in[1];
    // d_in[2] = i3d_feats (unused by reference)
    const float* subj_emb  = (const float*)d_in[3];
    const float* obj_emb   = (const float*)d_in[4];
    const float* pred_emb  = (const float*)d_in[5];
    const float* subj_w1   = (const float*)d_in[6];
    const float* subj_b1   = (const float*)d_in[7];
    const float* subj_w2   = (const float*)d_in[8];
    const float* subj_b2   = (const float*)d_in[9];
    const float* obj_w1    = (const float*)d_in[10];
    const float* obj_b1    = (const float*)d_in[11];
    const float* obj_w2    = (const float*)d_in[12];
    const float* obj_b2    = (const float*)d_in[13];
    const float* fuse_s_w1 = (const float*)d_in[14];
    const float* fuse_s_b1 = (const float*)d_in[15];
    const float* fuse_s_w2 = (const float*)d_in[16];
    const float* fuse_s_b2 = (const float*)d_in[17];
    const float* fuse_o_w1 = (const float*)d_in[18];
    const float* fuse_o_b1 = (const float*)d_in[19];
    const float* fuse_o_w2 = (const float*)d_in[20];
    const float* fuse_o_b2 = (const float*)d_in[21];
    const float* W_rs      = (const float*)d_in[22];
    const float* W_ro      = (const float*)d_in[23];
    const float* rel_w1    = (const float*)d_in[24];
    const float* rel_b1    = (const float*)d_in[25];
    const float* rel_w2    = (const float*)d_in[26];
    const float* rel_b2    = (const float*)d_in[27];
    float* out = (float*)d_out;

    // resolve scratch symbol addresses (no allocation)
    float *pX, *pY1, *pY2, *pA, *pB;
    float *pWf_s, *pWf_o, *pWcc_s, *pWcc_o;
    float *pc_subj, *pc_obj, *pbf_s, *pbf_o, *pcv_s, *pcv_o;
    cudaGetSymbolAddress((void**)&pX,     g_X);
    cudaGetSymbolAddress((void**)&pY1,    g_Y1);
    cudaGetSymbolAddress((void**)&pY2,    g_Y2);
    cudaGetSymbolAddress((void**)&pA,     g_A);
    cudaGetSymbolAddress((void**)&pB,     g_B);
    cudaGetSymbolAddress((void**)&pWf_s,  g_Wf_s);
    cudaGetSymbolAddress((void**)&pWf_o,  g_Wf_o);
    cudaGetSymbolAddress((void**)&pWcc_s, g_Wcc_s);
    cudaGetSymbolAddress((void**)&pWcc_o, g_Wcc_o);
    cudaGetSymbolAddress((void**)&pc_subj, g_c_subj);
    cudaGetSymbolAddress((void**)&pc_obj,  g_c_obj);
    cudaGetSymbolAddress((void**)&pbf_s,  g_bf_s);
    cudaGetSymbolAddress((void**)&pbf_o,  g_bf_o);
    cudaGetSymbolAddress((void**)&pcv_s,  g_cvec_s);
    cudaGetSymbolAddress((void**)&pcv_o,  g_cvec_o);

    // 1. pack + precompute folded weights
    pack_x_kernel<<<NROWS, 256>>>(roi, spatial);
    pre_vec_kernel<<<HH, 128>>>(subj_w1, subj_b1, obj_w1, obj_b1, rel_w1, rel_b1,
                                subj_emb, obj_emb, pred_emb, fuse_s_w1, fuse_o_w1);
    pre_wc_kernel<<<dim3(HH, 2), DD>>>(rel_w1, W_rs, W_ro);
    pre_wf_kernel<<<dim3(HH, 2), HH>>>(subj_w2, subj_b2, fuse_s_b1,
                                       obj_w2, obj_b2, fuse_o_b1);
    pre_wcc_kernel<<<dim3(HH, 2), HH>>>(fuse_s_w2, fuse_s_b2, fuse_o_w2, fuse_o_b2);

    dim3 ggrid(HH / 128, NROWS / 128);   // (4, 32)

    // 2. subject chain -> A
    gemm128_kernel<true ><<<ggrid, 256>>>(pX,  ROISPA, subj_w1, INW, pc_subj, pY1, HH, ROISPA);
    gemm128_kernel<true ><<<ggrid, 256>>>(pY1, HH,     pWf_s,   HH,  pbf_s,   pY2, HH, HH);
    gemm128_kernel<false><<<ggrid, 256>>>(pY2, HH,     pWcc_s,  HH,  pcv_s,   pA,  HH, HH);

    // 3. object chain -> B
    gemm128_kernel<true ><<<ggrid, 256>>>(pX,  ROISPA, obj_w1,  INW, pc_obj,  pY1, HH, ROISPA);
    gemm128_kernel<true ><<<ggrid, 256>>>(pY1, HH,     pWf_o,   HH,  pbf_o,   pY2, HH, HH);
    gemm128_kernel<false><<<ggrid, 256>>>(pY2, HH,     pWcc_o,  HH,  pcv_o,   pB,  HH, HH);

    // 4. pairwise GEMM: out[t,i,j,:] = relu(A_i - B_j + bias) @ W2^T + b2
    final_kernel<<<dim3(2, 32, 64), 256>>>(rel_w2, rel_b2, out);

    (void)in_sizes; (void)n_in; (void)out_size;
}

// round 3
// speedup vs baseline: 1.6107x; 1.6107x over previous
#include <cuda_runtime.h>
#include <cuda_bf16.h>
#include <cstdint>
#include <cstddef>

// ---------------- problem constants ----------------
#define TT      64
#define MM      64
#define NROWS   4096      // T*M
#define ROI     2048
#define SPA     4
#define WORD    300
#define ROISPA  2052      // ROI+SPA
#define INW     2352      // ROI+SPA+WORD
#define HH      512
#define DD      256
#define RELIN   556       // D + WORD

// ---------------- scratch (device globals; no allocation) ----------------
__device__ float g_X   [NROWS * ROISPA];   // packed [roi|spatial]
__device__ float g_Y1  [NROWS * HH];
__device__ float g_Y2  [NROWS * HH];
__device__ float g_A   [NROWS * HH];
__device__ float g_B   [NROWS * HH];

__device__ float g_Wsum_s[HH * DD], g_Wsum_o[HH * DD];
__device__ float g_Wc_s  [HH * DD], g_Wc_o  [HH * DD];
__device__ float g_Wf_s  [HH * HH], g_Wf_o  [HH * HH];
__device__ float g_Wcc_s [HH * HH], g_Wcc_o [HH * HH];

__device__ float g_c_subj[HH], g_c_obj[HH], g_bias512[HH];
__device__ float g_bf_s[HH], g_bf_o[HH], g_cvec_s[HH], g_cvec_o[HH];

// W2 split into bf16 hi/lo (256 x 512, K-major)
__device__ __nv_bfloat16 g_W2hi[DD * HH];
__device__ __nv_bfloat16 g_W2lo[DD * HH];

// ---------------- warp MMA helpers (sm_80-level, safe on sm_103 base target) --
__device__ __forceinline__ uint32_t smem_u32(const void* p) {
    uint32_t a;
    asm("{ .reg .u64 t; cvta.to.shared.u64 t, %1; cvt.u32.u64 %0, t; }"
        : "=r"(a) : "l"(p));
    return a;
}
__device__ __forceinline__ void ldsm4(uint32_t* r, uint32_t addr) {
    asm volatile("ldmatrix.sync.aligned.m8n8.x4.shared.b16 {%0,%1,%2,%3}, [%4];"
        : "=r"(r[0]), "=r"(r[1]), "=r"(r[2]), "=r"(r[3]) : "r"(addr));
}
__device__ __forceinline__ void mma_bf16(float* c, const uint32_t* a, const uint32_t* b) {
    asm volatile(
        "mma.sync.aligned.m16n8k16.row.col.f32.bf16.bf16.f32 "
        "{%0,%1,%2,%3}, {%4,%5,%6,%7}, {%8,%9}, {%0,%1,%2,%3};"
        : "+f"(c[0]), "+f"(c[1]), "+f"(c[2]), "+f"(c[3])
        : "r"(a[0]), "r"(a[1]), "r"(a[2]), "r"(a[3]), "r"(b[0]), "r"(b[1]));
}

// ---------------- pack X = [roi | spatial] ----------------
__global__ void pack_x_kernel(const float* __restrict__ roi,
                              const float* __restrict__ spa) {
    int r = blockIdx.x;
    for (int k = threadIdx.x; k < ROISPA; k += blockDim.x) {
        float v = (k < ROI) ? roi[(size_t)r * ROI + k]
                            : spa[(size_t)r * SPA + (k - ROI)];
        g_X[(size_t)r * ROISPA + k] = v;
    }
}

// ---------------- split rel_w2 into bf16 hi/lo ----------------
__global__ void split_w2_kernel(const float* __restrict__ w2) {
    int idx = blockIdx.x * 256 + threadIdx.x;   // grid 512 -> 131072
    float v = w2[idx];
    __nv_bfloat16 h = __float2bfloat16(v);
    g_W2hi[idx] = h;
    g_W2lo[idx] = __float2bfloat16(v - __bfloat162float(h));
}

// ---------------- precompute constant biases + Wsum ----------------
__global__ void pre_vec_kernel(const float* __restrict__ subj_w1, const float* __restrict__ subj_b1,
                               const float* __restrict__ obj_w1,  const float* __restrict__ obj_b1,
                               const float* __restrict__ rel_w1,  const float* __restrict__ rel_b1,
                               const float* __restrict__ subj_emb, const float* __restrict__ obj_emb,
                               const float* __restrict__ pred_emb,
                               const float* __restrict__ fuse_s_w1, const float* __restrict__ fuse_o_w1) {
    int h = blockIdx.x;
    int t = threadIdx.x;
    float s1 = 0.f, s2 = 0.f, s3 = 0.f;
    for (int w = t; w < WORD; w += 128) {
        s1 += subj_w1[(size_t)h * INW + ROISPA + w] * subj_emb[w];
        s2 += obj_w1 [(size_t)h * INW + ROISPA + w] * obj_emb[w];
        s3 += rel_w1 [(size_t)h * RELIN + DD + w]   * pred_emb[w];
    }
    for (int o = 16; o > 0; o >>= 1) {
        s1 += __shfl_down_sync(0xffffffffu, s1, o);
        s2 += __shfl_down_sync(0xffffffffu, s2, o);
        s3 += __shfl_down_sync(0xffffffffu, s3, o);
    }
    __shared__ float red[3][4];
    int wrp = t >> 5, lan = t & 31;
    if (lan == 0) { red[0][wrp] = s1; red[1][wrp] = s2; red[2][wrp] = s3; }
    __syncthreads();
    if (t == 0) {
        g_c_subj[h]  = red[0][0] + red[0][1] + red[0][2] + red[0][3] + subj_b1[h];
        g_c_obj[h]   = red[1][0] + red[1][1] + red[1][2] + red[1][3] + obj_b1[h];
        g_bias512[h] = red[2][0] + red[2][1] + red[2][2] + red[2][3] + rel_b1[h];
    }
    for (int d = t; d < DD; d += 128) {
        g_Wsum_s[h * DD + d] = fuse_s_w1[(size_t)h * (2*DD) + d] + fuse_s_w1[(size_t)h * (2*DD) + DD + d];
        g_Wsum_o[h * DD + d] = fuse_o_w1[(size_t)h * (2*DD) + d] + fuse_o_w1[(size_t)h * (2*DD) + DD + d];
    }
}

// ---------------- Wc[h,d] = sum_k rel_w1[h,k] * Wr[k,d] ----------------
__global__ void pre_wc_kernel(const float* __restrict__ rel_w1,
                              const float* __restrict__ W_rs,
                              const float* __restrict__ W_ro) {
    int h  = blockIdx.x;
    int br = blockIdx.y;
    int d  = threadIdx.x;
    const float* Wr = br ? W_ro : W_rs;
    float* out = br ? g_Wc_o : g_Wc_s;
    __shared__ float wd[DD];
    wd[d] = rel_w1[(size_t)h * RELIN + d];
    __syncthreads();
    float acc = 0.f;
    #pragma unroll 4
    for (int k = 0; k < DD; k++) acc = fmaf(wd[k], Wr[(size_t)k * DD + d], acc);
    out[h * DD + d] = acc;
}

// ---------------- Wf / bf ----------------
__global__ void pre_wf_kernel(const float* __restrict__ subj_w2, const float* __restrict__ subj_b2,
                              const float* __restrict__ fuse_s_b1,
                              const float* __restrict__ obj_w2,  const float* __restrict__ obj_b2,
                              const float* __restrict__ fuse_o_b1) {
    int h2 = blockIdx.x;
    int br = blockIdx.y;
    int t  = threadIdx.x;
    const float* Wsum = br ? g_Wsum_o : g_Wsum_s;
    const float* w2   = br ? obj_w2   : subj_w2;
    const float* b2   = br ? obj_b2   : subj_b2;
    const float* b1f  = br ? fuse_o_b1 : fuse_s_b1;
    float* Wf = br ? g_Wf_o : g_Wf_s;
    float* bf = br ? g_bf_o : g_bf_s;
    __shared__ float ws[DD];
    if (t < DD) ws[t] = Wsum[h2 * DD + t];
    __syncthreads();
    float acc = 0.f;
    #pragma unroll 4
    for (int d = 0; d < DD; d++) acc = fmaf(ws[d], w2[(size_t)d * HH + t], acc);
    Wf[(size_t)h2 * HH + t] = acc;
    if (t == 0) {
        float b = 0.f;
        for (int d = 0; d < DD; d++) b += ws[d] * b2[d];
        bf[h2] = b + b1f[h2];
    }
}

// ---------------- Wcc / cvec ----------------
__global__ void pre_wcc_kernel(const float* __restrict__ fuse_s_w2, const float* __restrict__ fuse_s_b2,
                               const float* __restrict__ fuse_o_w2, const float* __restrict__ fuse_o_b2) {
    int h  = blockIdx.x;
    int br = blockIdx.y;
    int t  = threadIdx.x;
    const float* Wc  = br ? g_Wc_o : g_Wc_s;
    const float* fw2 = br ? fuse_o_w2 : fuse_s_w2;
    const float* fb2 = br ? fuse_o_b2 : fuse_s_b2;
    float* Wcc  = br ? g_Wcc_o : g_Wcc_s;
    float* cvec = br ? g_cvec_o : g_cvec_s;
    __shared__ float ws[DD];
    if (t < DD) ws[t] = Wc[h * DD + t];
    __syncthreads();
    float acc = 0.f;
    #pragma unroll 4
    for (int d = 0; d < DD; d++) acc = fmaf(ws[d], fw2[(size_t)d * HH + t], acc);
    Wcc[(size_t)h * HH + t] = acc;
    if (t == 0) {
        float b = 0.f;
        for (int d = 0; d < DD; d++) b += ws[d] * fb2[d];
        cvec[h] = b;
    }
}

// ---------------- generic NT GEMM (chain, fp32) ----------------
template<bool RELU>
__global__ __launch_bounds__(256, 2)
void gemm128_kernel(const float* __restrict__ X, int ldx,
                    const float* __restrict__ W, int ldw,
                    const float* __restrict__ bias,
                    float* __restrict__ C, int N, int K) {
    __shared__ float Xs[16][132];
    __shared__ float Ws[16][132];
    const int m0 = blockIdx.y * 128;
    const int n0 = blockIdx.x * 128;
    const int tid = threadIdx.x;
    const int tr = tid >> 4, tc = tid & 15;

    float acc[8][8];
    #pragma unroll
    for (int i = 0; i < 8; i++)
        #pragma unroll
        for (int j = 0; j < 8; j++) acc[i][j] = 0.f;

    for (int k0 = 0; k0 < K; k0 += 16) {
        #pragma unroll
        for (int e = 0; e < 2; e++) {
            int idx = e * 256 + tid;
            int m = idx >> 2, kq = (idx & 3) * 4;
            float4 v = make_float4(0.f, 0.f, 0.f, 0.f);
            if (k0 + kq < K)
                v = *reinterpret_cast<const float4*>(&X[(size_t)(m0 + m) * ldx + k0 + kq]);
            Xs[kq + 0][m] = v.x; Xs[kq + 1][m] = v.y; Xs[kq + 2][m] = v.z; Xs[kq + 3][m] = v.w;
        }
        #pragma unroll
        for (int e = 0; e < 2; e++) {
            int idx = e * 256 + tid;
            int n = idx >> 2, kq = (idx & 3) * 4;
            float4 v = make_float4(0.f, 0.f, 0.f, 0.f);
            if (k0 + kq < K)
                v = *reinterpret_cast<const float4*>(&W[(size_t)(n0 + n) * ldw + k0 + kq]);
            Ws[kq + 0][n] = v.x; Ws[kq + 1][n] = v.y; Ws[kq + 2][n] = v.z; Ws[kq + 3][n] = v.w;
        }
        __syncthreads();
        #pragma unroll
        for (int kk = 0; kk < 16; kk++) {
            float4 a0 = *reinterpret_cast<const float4*>(&Xs[kk][tr * 8]);
            float4 a1 = *reinterpret_cast<const float4*>(&Xs[kk][tr * 8 + 4]);
            float4 b0 = *reinterpret_cast<const float4*>(&Ws[kk][tc * 8]);
            float4 b1 = *reinterpret_cast<const float4*>(&Ws[kk][tc * 8 + 4]);
            float a[8] = {a0.x, a0.y, a0.z, a0.w, a1.x, a1.y, a1.z, a1.w};
            float b[8] = {b0.x, b0.y, b0.z, b0.w, b1.x, b1.y, b1.z, b1.w};
            #pragma unroll
            for (int i = 0; i < 8; i++)
                #pragma unroll
                for (int j = 0; j < 8; j++)
                    acc[i][j] = fmaf(a[i], b[j], acc[i][j]);
        }
        __syncthreads();
    }

    float bv[8];
    #pragma unroll
    for (int j = 0; j < 8; j++) bv[j] = bias[n0 + tc * 8 + j];
    #pragma unroll
    for (int i = 0; i < 8; i++) {
        int m = m0 + tr * 8 + i;
        float r[8];
        #pragma unroll
        for (int j = 0; j < 8; j++) {
            float v = acc[i][j] + bv[j];
            r[j] = RELU ? fmaxf(v, 0.f) : v;
        }
        float4* cp = reinterpret_cast<float4*>(&C[(size_t)m * N + n0 + tc * 8]);
        cp[0] = make_float4(r[0], r[1], r[2], r[3]);
        cp[1] = make_float4(r[4], r[5], r[6], r[7]);
    }
}

// ================= HMMA pairwise kernel =================
// out[t,i,j,n] = sum_k relu(A[ti,k]-B[tj,k]+bias[k]) * W2[n,k] + b2[n]
// grid (2 nTiles, 32 iPairs, 64 t), 256 threads (8 warps = 4m x 2n).
// CTA tile: 128 pairs (2 i x 64 j) x 128 n, K=512 in 16 chunks of 32.
// 3-term bf16 split: acc += Hh*Wh + Hh*Wl + Hl*Wh via mma.sync m16n8k16.

#define PBK   32              // k-chunk (bf16 elements)
#define PSTR  80              // smem row stride bytes (40 bf16, pad 8)
// smem byte offsets
#define POFF_HH   0
#define POFF_HL   10240
#define POFF_WH   20480
#define POFF_WL   30720
#define POFF_B    40960       // 64 x 36 floats
#define POFF_A    50176       // 2 x 32 floats
#define POFF_BIAS 50432       // 32 floats
#define POFF_B2   50560       // 128 floats
#define PSMEM     51072

__global__ __launch_bounds__(256, 2)
void pairwise_hmma_kernel(const float* __restrict__ b2v,
                          float* __restrict__ out) {
    extern __shared__ char smem[];
    const uint32_t su = smem_u32(smem);
    float* Bs    = reinterpret_cast<float*>(smem + POFF_B);
    float* As    = reinterpret_cast<float*>(smem + POFF_A);
    float* biasS = reinterpret_cast<float*>(smem + POFF_BIAS);
    float* bs2   = reinterpret_cast<float*>(smem + POFF_B2);

    const int tid  = threadIdx.x;
    const int wid  = tid >> 5;
    const int lane = tid & 31;
    const int wm   = wid >> 1;          // 0..3 (m tile of 32 rows)
    const int wn   = wid & 1;           // 0..1 (n tile of 64 cols)

    const int n0  = blockIdx.x * 128;
    const int ib2 = blockIdx.y * 2;
    const int t   = blockIdx.z;

    if (tid < 128) bs2[tid] = b2v[n0 + tid];

    const size_t arow0 = (size_t)(t * 64 + ib2) * HH;
    const size_t brow0 = (size_t)(t * 64) * HH;

    // per-lane ldmatrix offsets (bytes)
    const uint32_t h_off = (uint32_t)((lane & 15) * PSTR + (lane >> 4) * 16);
    const uint32_t w_off = (uint32_t)(((lane & 7) + ((lane >> 4) << 3)) * PSTR
                                      + ((lane >> 3) & 1) * 16);

    float acc[2][8][4];
    #pragma unroll
    for (int mb = 0; mb < 2; mb++)
        #pragma unroll
        for (int nb = 0; nb < 8; nb++)
            #pragma unroll
            for (int q = 0; q < 4; q++) acc[mb][nb][q] = 0.f;

    for (int c = 0; c < 16; c++) {
        const int k0 = c * PBK;
        __syncthreads();    // previous chunk's mma reads done

        // ---- stage A / bias ----
        if (tid < 64) {
            int r = tid >> 5, k = tid & 31;
            As[r * 32 + k] = g_A[arow0 + (size_t)r * HH + k0 + k];
        } else if (tid < 96) {
            biasS[tid - 64] = g_bias512[k0 + tid - 64];
        }
        // ---- stage B (64 x 32 fp32, stride 36) ----
        #pragma unroll
        for (int e = 0; e < 2; e++) {
            int idx = e * 256 + tid;
            int j = idx >> 3, q = idx & 7;
            float4 v = *reinterpret_cast<const float4*>(&g_B[brow0 + (size_t)j * HH + k0 + q * 4]);
            *reinterpret_cast<float4*>(&Bs[j * 36 + q * 4]) = v;
        }
        // ---- stage W hi/lo (128 x 32 bf16 each, stride 80B) ----
        #pragma unroll
        for (int e = 0; e < 2; e++) {
            int idx = e * 256 + tid;
            int n = idx >> 2, q = idx & 3;
            uint4 vh = *reinterpret_cast<const uint4*>(&g_W2hi[(size_t)(n0 + n) * HH + k0 + q * 8]);
            *reinterpret_cast<uint4*>(smem + POFF_WH + n * PSTR + q * 16) = vh;
            uint4 vl = *reinterpret_cast<const uint4*>(&g_W2lo[(size_t)(n0 + n) * HH + k0 + q * 8]);
            *reinterpret_cast<uint4*>(smem + POFF_WL + n * PSTR + q * 16) = vl;
        }
        __syncthreads();    // A/B/bias/W visible

        // ---- build Hh/Hl (128 rows x 32 k, bf16, stride 80B) ----
        #pragma unroll
        for (int e = 0; e < 8; e++) {
            int idx = e * 256 + tid;        // 0..2047
            int p  = idx >> 4;              // 0..127
            int kp = idx & 15;              // k-pair
            int k  = kp * 2;
            int i  = p >> 6, j = p & 63;
            float a0 = As[i * 32 + k],     a1 = As[i * 32 + k + 1];
            float b0 = Bs[j * 36 + k],     b1 = Bs[j * 36 + k + 1];
            float v0 = fmaxf(a0 - b0 + biasS[k],     0.f);
            float v1 = fmaxf(a1 - b1 + biasS[k + 1], 0.f);
            __nv_bfloat16 h0 = __float2bfloat16(v0);
            __nv_bfloat16 h1 = __float2bfloat16(v1);
            __nv_bfloat16 l0 = __float2bfloat16(v0 - __bfloat162float(h0));
            __nv_bfloat16 l1 = __float2bfloat16(v1 - __bfloat162float(h1));
            uint32_t hp = ((uint32_t)__bfloat16_as_ushort(h1) << 16) | __bfloat16_as_ushort(h0);
            uint32_t lp = ((uint32_t)__bfloat16_as_ushort(l1) << 16) | __bfloat16_as_ushort(l0);
            *reinterpret_cast<uint32_t*>(smem + POFF_HH + p * PSTR + k * 2) = hp;
            *reinterpret_cast<uint32_t*>(smem + POFF_HL + p * PSTR + k * 2) = lp;
        }
        __syncthreads();    // H staged

        // ---- MMA: 3 terms over this chunk ----
        #pragma unroll
        for (int ks = 0; ks < 2; ks++) {
            #pragma unroll
            for (int term = 0; term < 3; term++) {
                const uint32_t hbase = su + (term == 2 ? POFF_HL : POFF_HH)
                                       + wm * (32 * PSTR) + ks * 32 + h_off;
                const uint32_t wbase = su + (term == 1 ? POFF_WL : POFF_WH)
                                       + wn * (64 * PSTR) + ks * 32 + w_off;
                uint32_t a[2][4], b[4][4];
                #pragma unroll
                for (int mb = 0; mb < 2; mb++)
                    ldsm4(a[mb], hbase + mb * (16 * PSTR));
                #pragma unroll
                for (int g = 0; g < 4; g++)
                    ldsm4(b[g], wbase + g * (16 * PSTR));
                #pragma unroll
                for (int mb = 0; mb < 2; mb++)
                    #pragma unroll
                    for (int g = 0; g < 4; g++) {
                        mma_bf16(acc[mb][g * 2 + 0], a[mb], &b[g][0]);
                        mma_bf16(acc[mb][g * 2 + 1], a[mb], &b[g][2]);
                    }
            }
        }
    }

    // ---- epilogue ----
    const int qr = lane >> 2, qc = (lane & 3) * 2;
    #pragma unroll
    for (int mb = 0; mb < 2; mb++) {
        int rA = wm * 32 + mb * 16 + qr;
        int rB = rA + 8;
        float* oA = out + ((size_t)(t * 64 + ib2 + (rA >> 6)) * 64 + (rA & 63)) * 256
                        + n0 + wn * 64 + qc;
        float* oB = out + ((size_t)(t * 64 + ib2 + (rB >> 6)) * 64 + (rB & 63)) * 256
                        + n0 + wn * 64 + qc;
        #pragma unroll
        for (int nb = 0; nb < 8; nb++) {
            int ln = wn * 64 + nb * 8 + qc;
            float2 vA = make_float2(acc[mb][nb][0] + bs2[ln],
                                    acc[mb][nb][1] + bs2[ln + 1]);
            float2 vB = make_float2(acc[mb][nb][2] + bs2[ln],
                                    acc[mb][nb][3] + bs2[ln + 1]);
            *reinterpret_cast<float2*>(oA + nb * 8) = vA;
            *reinterpret_cast<float2*>(oB + nb * 8) = vB;
        }
    }
}

// ---------------- host launch ----------------
extern "C" void kernel_launch(void* const* d_in, const int* in_sizes, int n_in,
                              void* d_out, int out_size) {
    const float* roi       = (const float*)d_in[0];
    const float* spatial   = (const float*)d_in[1];
    const float* subj_emb  = (const float*)d_in[3];
    const float* obj_emb   = (const float*)d_in[4];
    const float* pred_emb  = (const float*)d_in[5];
    const float* subj_w1   = (const float*)d_in[6];
    const float* subj_b1   = (const float*)d_in[7];
    const float* subj_w2   = (const float*)d_in[8];
    const float* subj_b2   = (const float*)d_in[9];
    const float* obj_w1    = (const float*)d_in[10];
    const float* obj_b1    = (const float*)d_in[11];
    const float* obj_w2    = (const float*)d_in[12];
    const float* obj_b2    = (const float*)d_in[13];
    const float* fuse_s_w1 = (const float*)d_in[14];
    const float* fuse_s_b1 = (const float*)d_in[15];
    const float* fuse_s_w2 = (const float*)d_in[16];
    const float* fuse_s_b2 = (const float*)d_in[17];
    const float* fuse_o_w1 = (const float*)d_in[18];
    const float* fuse_o_b1 = (const float*)d_in[19];
    const float* fuse_o_w2 = (const float*)d_in[20];
    const float* fuse_o_b2 = (const float*)d_in[21];
    const float* W_rs      = (const float*)d_in[22];
    const float* W_ro      = (const float*)d_in[23];
    const float* rel_w1    = (const float*)d_in[24];
    const float* rel_b1    = (const float*)d_in[25];
    const float* rel_w2    = (const float*)d_in[26];
    const float* rel_b2    = (const float*)d_in[27];
    float* out = (float*)d_out;

    float *pX, *pY1, *pY2, *pA, *pB;
    float *pWf_s, *pWf_o, *pWcc_s, *pWcc_o;
    float *pc_subj, *pc_obj, *pbf_s, *pbf_o, *pcv_s, *pcv_o;
    cudaGetSymbolAddress((void**)&pX,     g_X);
    cudaGetSymbolAddress((void**)&pY1,    g_Y1);
    cudaGetSymbolAddress((void**)&pY2,    g_Y2);
    cudaGetSymbolAddress((void**)&pA,     g_A);
    cudaGetSymbolAddress((void**)&pB,     g_B);
    cudaGetSymbolAddress((void**)&pWf_s,  g_Wf_s);
    cudaGetSymbolAddress((void**)&pWf_o,  g_Wf_o);
    cudaGetSymbolAddress((void**)&pWcc_s, g_Wcc_s);
    cudaGetSymbolAddress((void**)&pWcc_o, g_Wcc_o);
    cudaGetSymbolAddress((void**)&pc_subj, g_c_subj);
    cudaGetSymbolAddress((void**)&pc_obj,  g_c_obj);
    cudaGetSymbolAddress((void**)&pbf_s,  g_bf_s);
    cudaGetSymbolAddress((void**)&pbf_o,  g_bf_o);
    cudaGetSymbolAddress((void**)&pcv_s,  g_cvec_s);
    cudaGetSymbolAddress((void**)&pcv_o,  g_cvec_o);

    static bool attr_set = false;
    if (!attr_set) {
        cudaFuncSetAttribute(pairwise_hmma_kernel,
                             cudaFuncAttributeMaxDynamicSharedMemorySize, PSMEM);
        attr_set = true;
    }

    // 1. pack + precompute folded weights
    pack_x_kernel<<<NROWS, 256>>>(roi, spatial);
    split_w2_kernel<<<512, 256>>>(rel_w2);
    pre_vec_kernel<<<HH, 128>>>(subj_w1, subj_b1, obj_w1, obj_b1, rel_w1, rel_b1,
                                subj_emb, obj_emb, pred_emb, fuse_s_w1, fuse_o_w1);
    pre_wc_kernel<<<dim3(HH, 2), DD>>>(rel_w1, W_rs, W_ro);
    pre_wf_kernel<<<dim3(HH, 2), HH>>>(subj_w2, subj_b2, fuse_s_b1,
                                       obj_w2, obj_b2, fuse_o_b1);
    pre_wcc_kernel<<<dim3(HH, 2), HH>>>(fuse_s_w2, fuse_s_b2, fuse_o_w2, fuse_o_b2);

    dim3 ggrid(HH / 128, NROWS / 128);

    // 2. subject chain -> A
    gemm128_kernel<true ><<<ggrid, 256>>>(pX,  ROISPA, subj_w1, INW, pc_subj, pY1, HH, ROISPA);
    gemm128_kernel<true ><<<ggrid, 256>>>(pY1, HH,     pWf_s,   HH,  pbf_s,   pY2, HH, HH);
    gemm128_kernel<false><<<ggrid, 256>>>(pY2, HH,     pWcc_s,  HH,  pcv_s,   pA,  HH, HH);

    // 3. object chain -> B
    gemm128_kernel<true ><<<ggrid, 256>>>(pX,  ROISPA, obj_w1,  INW, pc_obj,  pY1, HH, ROISPA);
    gemm128_kernel<true ><<<ggrid, 256>>>(pY1, HH,     pWf_o,   HH,  pbf_o,   pY2, HH, HH);
    gemm128_kernel<false><<<ggrid, 256>>>(pY2, HH,     pWcc_o,  HH,  pcv_o,   pB,  HH, HH);

    // 4. pairwise GEMM on tensor cores (HMMA)
    pairwise_hmma_kernel<<<dim3(2, 32, 64), 256, PSMEM>>>(rel_b2, out);

    (void)in_sizes; (void)n_in; (void)out_size;
}

// round 4
// speedup vs baseline: 2.3721x; 1.4727x over previous
#include <cuda_runtime.h>
#include <cuda_bf16.h>
#include <cstdint>
#include <cstddef>

// ---------------- problem constants ----------------
#define TT      64
#define MM      64
#define NROWS   4096      // T*M
#define ROI     2048
#define SPA     4
#define WORD    300
#define ROISPA  2052      // ROI+SPA
#define INW     2352      // ROI+SPA+WORD
#define HH      512
#define DD      256
#define RELIN   556       // D + WORD
#define KP1     2080      // ROISPA padded to 65*32

// ---------------- scratch (device globals; no allocation) ----------------
// layer-1 input, bf16 hi/lo, padded to KP1
__device__ __nv_bfloat16 g_Xh[NROWS * KP1], g_Xl[NROWS * KP1];
// layer-1 weights (cols 0..2051 of w1, zero-padded), bf16 hi/lo, per branch
__device__ __nv_bfloat16 g_W1h_s[HH * KP1], g_W1l_s[HH * KP1];
__device__ __nv_bfloat16 g_W1h_o[HH * KP1], g_W1l_o[HH * KP1];
// intermediate activations bf16 hi/lo
__device__ __nv_bfloat16 g_Y1h_s[NROWS * HH], g_Y1l_s[NROWS * HH];
__device__ __nv_bfloat16 g_Y1h_o[NROWS * HH], g_Y1l_o[NROWS * HH];
__device__ __nv_bfloat16 g_Y2h_s[NROWS * HH], g_Y2l_s[NROWS * HH];
__device__ __nv_bfloat16 g_Y2h_o[NROWS * HH], g_Y2l_o[NROWS * HH];
// folded weights bf16 hi/lo
__device__ __nv_bfloat16 g_Wfh_s[HH * HH], g_Wfl_s[HH * HH];
__device__ __nv_bfloat16 g_Wfh_o[HH * HH], g_Wfl_o[HH * HH];
__device__ __nv_bfloat16 g_Wcch_s[HH * HH], g_Wccl_s[HH * HH];
__device__ __nv_bfloat16 g_Wcch_o[HH * HH], g_Wccl_o[HH * HH];
// fp32 chain outputs for pairwise stage
__device__ float g_A[NROWS * HH];
__device__ float g_B[NROWS * HH];
// fp32 precompute intermediates
__device__ float g_Wsum_s[HH * DD], g_Wsum_o[HH * DD];
__device__ float g_Wc_s  [HH * DD], g_Wc_o  [HH * DD];
__device__ float g_c_subj[HH], g_c_obj[HH], g_bias512[HH];
__device__ float g_bf_s[HH], g_bf_o[HH], g_cvec_s[HH], g_cvec_o[HH];
// pairwise W2 split
__device__ __nv_bfloat16 g_W2hi[DD * HH];
__device__ __nv_bfloat16 g_W2lo[DD * HH];

// ---------------- warp MMA helpers (sm_80-level, safe on sm_103 base target) --
__device__ __forceinline__ uint32_t smem_u32(const void* p) {
    uint32_t a;
    asm("{ .reg .u64 t; cvta.to.shared.u64 t, %1; cvt.u32.u64 %0, t; }"
        : "=r"(a) : "l"(p));
    return a;
}
__device__ __forceinline__ void ldsm4(uint32_t* r, uint32_t addr) {
    asm volatile("ldmatrix.sync.aligned.m8n8.x4.shared.b16 {%0,%1,%2,%3}, [%4];"
        : "=r"(r[0]), "=r"(r[1]), "=r"(r[2]), "=r"(r[3]) : "r"(addr));
}
__device__ __forceinline__ void mma_bf16(float* c, const uint32_t* a, const uint32_t* b) {
    asm volatile(
        "mma.sync.aligned.m16n8k16.row.col.f32.bf16.bf16.f32 "
        "{%0,%1,%2,%3}, {%4,%5,%6,%7}, {%8,%9}, {%0,%1,%2,%3};"
        : "+f"(c[0]), "+f"(c[1]), "+f"(c[2]), "+f"(c[3])
        : "r"(a[0]), "r"(a[1]), "r"(a[2]), "r"(a[3]), "r"(b[0]), "r"(b[1]));
}
__device__ __forceinline__ void split_bf16(float v, __nv_bfloat16& h, __nv_bfloat16& l) {
    h = __float2bfloat16(v);
    l = __float2bfloat16(v - __bfloat162float(h));
}
__device__ __forceinline__ uint32_t pack_bf(__nv_bfloat16 a, __nv_bfloat16 b) {
    return ((uint32_t)__bfloat16_as_ushort(b) << 16) | __bfloat16_as_ushort(a);
}

// ---------------- pack X = [roi | spatial | 0pad] -> bf16 hi/lo ----------------
__global__ void pack_x_kernel(const float* __restrict__ roi,
                              const float* __restrict__ spa) {
    int r = blockIdx.x;
    for (int k = threadIdx.x; k < KP1; k += blockDim.x) {
        float v = 0.f;
        if (k < ROI)         v = roi[(size_t)r * ROI + k];
        else if (k < ROISPA) v = spa[(size_t)r * SPA + (k - ROI)];
        __nv_bfloat16 h, l; split_bf16(v, h, l);
        g_Xh[(size_t)r * KP1 + k] = h;
        g_Xl[(size_t)r * KP1 + k] = l;
    }
}

// ---------------- split layer-1 weights (first 2052 cols, pad) ----------------
__global__ void split_w1_kernel(const float* __restrict__ s_w1,
                                const float* __restrict__ o_w1) {
    int idx = blockIdx.x * 256 + threadIdx.x;   // over HH*KP1 = 1064960
    if (idx >= HH * KP1) return;
    int n = idx / KP1, k = idx - n * KP1;
    float vs = (k < ROISPA) ? s_w1[(size_t)n * INW + k] : 0.f;
    float vo = (k < ROISPA) ? o_w1[(size_t)n * INW + k] : 0.f;
    __nv_bfloat16 h, l;
    split_bf16(vs, h, l); g_W1h_s[idx] = h; g_W1l_s[idx] = l;
    split_bf16(vo, h, l); g_W1h_o[idx] = h; g_W1l_o[idx] = l;
}

// ---------------- split rel_w2 into bf16 hi/lo ----------------
__global__ void split_w2_kernel(const float* __restrict__ w2) {
    int idx = blockIdx.x * 256 + threadIdx.x;
    float v = w2[idx];
    __nv_bfloat16 h, l; split_bf16(v, h, l);
    g_W2hi[idx] = h;
    g_W2lo[idx] = l;
}

// ---------------- precompute constant biases + Wsum ----------------
__global__ void pre_vec_kernel(const float* __restrict__ subj_w1, const float* __restrict__ subj_b1,
                               const float* __restrict__ obj_w1,  const float* __restrict__ obj_b1,
                               const float* __restrict__ rel_w1,  const float* __restrict__ rel_b1,
                               const float* __restrict__ subj_emb, const float* __restrict__ obj_emb,
                               const float* __restrict__ pred_emb,
                               const float* __restrict__ fuse_s_w1, const float* __restrict__ fuse_o_w1) {
    int h = blockIdx.x;
    int t = threadIdx.x;
    float s1 = 0.f, s2 = 0.f, s3 = 0.f;
    for (int w = t; w < WORD; w += 128) {
        s1 += subj_w1[(size_t)h * INW + ROISPA + w] * subj_emb[w];
        s2 += obj_w1 [(size_t)h * INW + ROISPA + w] * obj_emb[w];
        s3 += rel_w1 [(size_t)h * RELIN + DD + w]   * pred_emb[w];
    }
    for (int o = 16; o > 0; o >>= 1) {
        s1 += __shfl_down_sync(0xffffffffu, s1, o);
        s2 += __shfl_down_sync(0xffffffffu, s2, o);
        s3 += __shfl_down_sync(0xffffffffu, s3, o);
    }
    __shared__ float red[3][4];
    int wrp = t >> 5, lan = t & 31;
    if (lan == 0) { red[0][wrp] = s1; red[1][wrp] = s2; red[2][wrp] = s3; }
    __syncthreads();
    if (t == 0) {
        g_c_subj[h]  = red[0][0] + red[0][1] + red[0][2] + red[0][3] + subj_b1[h];
        g_c_obj[h]   = red[1][0] + red[1][1] + red[1][2] + red[1][3] + obj_b1[h];
        g_bias512[h] = red[2][0] + red[2][1] + red[2][2] + red[2][3] + rel_b1[h];
    }
    for (int d = t; d < DD; d += 128) {
        g_Wsum_s[h * DD + d] = fuse_s_w1[(size_t)h * (2*DD) + d] + fuse_s_w1[(size_t)h * (2*DD) + DD + d];
        g_Wsum_o[h * DD + d] = fuse_o_w1[(size_t)h * (2*DD) + d] + fuse_o_w1[(size_t)h * (2*DD) + DD + d];
    }
}

// ---------------- Wc[h,d] = sum_k rel_w1[h,k] * Wr[k,d] ----------------
__global__ void pre_wc_kernel(const float* __restrict__ rel_w1,
                              const float* __restrict__ W_rs,
                              const float* __restrict__ W_ro) {
    int h  = blockIdx.x;
    int br = blockIdx.y;
    int d  = threadIdx.x;
    const float* Wr = br ? W_ro : W_rs;
    float* out = br ? g_Wc_o : g_Wc_s;
    __shared__ float wd[DD];
    wd[d] = rel_w1[(size_t)h * RELIN + d];
    __syncthreads();
    float acc = 0.f;
    #pragma unroll 4
    for (int k = 0; k < DD; k++) acc = fmaf(wd[k], Wr[(size_t)k * DD + d], acc);
    out[h * DD + d] = acc;
}

// ---------------- Wf (bf16 hi/lo) / bf ----------------
__global__ void pre_wf_kernel(const float* __restrict__ subj_w2, const float* __restrict__ subj_b2,
                              const float* __restrict__ fuse_s_b1,
                              const float* __restrict__ obj_w2,  const float* __restrict__ obj_b2,
                              const float* __restrict__ fuse_o_b1) {
    int h2 = blockIdx.x;
    int br = blockIdx.y;
    int t  = threadIdx.x;
    const float* Wsum = br ? g_Wsum_o : g_Wsum_s;
    const float* w2   = br ? obj_w2   : subj_w2;
    const float* b2   = br ? obj_b2   : subj_b2;
    const float* b1f  = br ? fuse_o_b1 : fuse_s_b1;
    __nv_bfloat16* Wfh = br ? g_Wfh_o : g_Wfh_s;
    __nv_bfloat16* Wfl = br ? g_Wfl_o : g_Wfl_s;
    float* bf = br ? g_bf_o : g_bf_s;
    __shared__ float ws[DD];
    if (t < DD) ws[t] = Wsum[h2 * DD + t];
    __syncthreads();
    float acc = 0.f;
    #pragma unroll 4
    for (int d = 0; d < DD; d++) acc = fmaf(ws[d], w2[(size_t)d * HH + t], acc);
    __nv_bfloat16 h, l; split_bf16(acc, h, l);
    Wfh[(size_t)h2 * HH + t] = h;
    Wfl[(size_t)h2 * HH + t] = l;
    if (t == 0) {
        float b = 0.f;
        for (int d = 0; d < DD; d++) b += ws[d] * b2[d];
        bf[h2] = b + b1f[h2];
    }
}

// ---------------- Wcc (bf16 hi/lo) / cvec ----------------
__global__ void pre_wcc_kernel(const float* __restrict__ fuse_s_w2, const float* __restrict__ fuse_s_b2,
                               const float* __restrict__ fuse_o_w2, const float* __restrict__ fuse_o_b2) {
    int h  = blockIdx.x;
    int br = blockIdx.y;
    int t  = threadIdx.x;
    const float* Wc  = br ? g_Wc_o : g_Wc_s;
    const float* fw2 = br ? fuse_o_w2 : fuse_s_w2;
    const float* fb2 = br ? fuse_o_b2 : fuse_s_b2;
    __nv_bfloat16* Wcch = br ? g_Wcch_o : g_Wcch_s;
    __nv_bfloat16* Wccl = br ? g_Wccl_o : g_Wccl_s;
    float* cvec = br ? g_cvec_o : g_cvec_s;
    __shared__ float ws[DD];
    if (t < DD) ws[t] = Wc[h * DD + t];
    __syncthreads();
    float acc = 0.f;
    #pragma unroll 4
    for (int d = 0; d < DD; d++) acc = fmaf(ws[d], fw2[(size_t)d * HH + t], acc);
    __nv_bfloat16 hb, lb; split_bf16(acc, hb, lb);
    Wcch[(size_t)h * HH + t] = hb;
    Wccl[(size_t)h * HH + t] = lb;
    if (t == 0) {
        float b = 0.f;
        for (int d = 0; d < DD; d++) b += ws[d] * fb2[d];
        cvec[h] = b;
    }
}

// ================= chain HMMA GEMM (bf16 3-term split) =================
// C[m,n] = act(sum_k X[m,k]*W[n,k] + bias[n]); X,W given as bf16 hi/lo.
// grid (N/128, M/128, 2 branches), 256 threads (8 warps = 4m x 2n).
#define CPSTR     80
#define COFF_XH   0
#define COFF_XL   10240
#define COFF_WH   20480
#define COFF_WL   30720
#define COFF_BIAS 40960
#define CSMEM     41472

template<bool RELU, bool BF16OUT>
__global__ __launch_bounds__(256, 2)
void chain_hmma_kernel(const __nv_bfloat16* __restrict__ Xh0, const __nv_bfloat16* __restrict__ Xl0,
                       const __nv_bfloat16* __restrict__ Xh1, const __nv_bfloat16* __restrict__ Xl1,
                       int ldx,
                       const __nv_bfloat16* __restrict__ Wh0, const __nv_bfloat16* __restrict__ Wl0,
                       const __nv_bfloat16* __restrict__ Wh1, const __nv_bfloat16* __restrict__ Wl1,
                       const float* __restrict__ bias0, const float* __restrict__ bias1,
                       float* __restrict__ C0, float* __restrict__ C1,
                       __nv_bfloat16* __restrict__ Ch0, __nv_bfloat16* __restrict__ Cl0,
                       __nv_bfloat16* __restrict__ Ch1, __nv_bfloat16* __restrict__ Cl1,
                       int N, int K) {
    __shared__ char smem[CSMEM];
    const uint32_t su = smem_u32(smem);
    float* biasS = reinterpret_cast<float*>(smem + COFF_BIAS);

    const int tid  = threadIdx.x;
    const int wid  = tid >> 5;
    const int lane = tid & 31;
    const int wm   = wid >> 1;
    const int wn   = wid & 1;
    const int n0   = blockIdx.x * 128;
    const int m0   = blockIdx.y * 128;
    const int br   = blockIdx.z;

    const __nv_bfloat16* Xh = br ? Xh1 : Xh0;
    const __nv_bfloat16* Xl = br ? Xl1 : Xl0;
    const __nv_bfloat16* Wh = br ? Wh1 : Wh0;
    const __nv_bfloat16* Wl = br ? Wl1 : Wl0;
    const float* bias = br ? bias1 : bias0;

    if (tid < 128) biasS[tid] = bias[n0 + tid];

    const uint32_t h_off = (uint32_t)((lane & 15) * CPSTR + (lane >> 4) * 16);
    const uint32_t w_off = (uint32_t)(((lane & 7) + ((lane >> 4) << 3)) * CPSTR
                                      + ((lane >> 3) & 1) * 16);

    float acc[2][8][4];
    #pragma unroll
    for (int mb = 0; mb < 2; mb++)
        #pragma unroll
        for (int nb = 0; nb < 8; nb++)
            #pragma unroll
            for (int q = 0; q < 4; q++) acc[mb][nb][q] = 0.f;

    for (int k0 = 0; k0 < K; k0 += 32) {
        __syncthreads();
        #pragma unroll
        for (int e = 0; e < 2; e++) {
            int idx = e * 256 + tid;
            int r = idx >> 2, q = idx & 3;
            *reinterpret_cast<uint4*>(smem + COFF_XH + r * CPSTR + q * 16) =
                *reinterpret_cast<const uint4*>(&Xh[(size_t)(m0 + r) * ldx + k0 + q * 8]);
            *reinterpret_cast<uint4*>(smem + COFF_XL + r * CPSTR + q * 16) =
                *reinterpret_cast<const uint4*>(&Xl[(size_t)(m0 + r) * ldx + k0 + q * 8]);
            *reinterpret_cast<uint4*>(smem + COFF_WH + r * CPSTR + q * 16) =
                *reinterpret_cast<const uint4*>(&Wh[(size_t)(n0 + r) * K + k0 + q * 8]);
            *reinterpret_cast<uint4*>(smem + COFF_WL + r * CPSTR + q * 16) =
                *reinterpret_cast<const uint4*>(&Wl[(size_t)(n0 + r) * K + k0 + q * 8]);
        }
        __syncthreads();

        #pragma unroll
        for (int ks = 0; ks < 2; ks++) {
            #pragma unroll
            for (int term = 0; term < 3; term++) {
                const uint32_t hbase = su + (term == 2 ? COFF_XL : COFF_XH)
                                       + wm * (32 * CPSTR) + ks * 32 + h_off;
                const uint32_t wbase = su + (term == 1 ? COFF_WL : COFF_WH)
                                       + wn * (64 * CPSTR) + ks * 32 + w_off;
                uint32_t a[2][4], b[4][4];
                #pragma unroll
                for (int mb = 0; mb < 2; mb++)
                    ldsm4(a[mb], hbase + mb * (16 * CPSTR));
                #pragma unroll
                for (int g = 0; g < 4; g++)
                    ldsm4(b[g], wbase + g * (16 * CPSTR));
                #pragma unroll
                for (int mb = 0; mb < 2; mb++)
                    #pragma unroll
                    for (int g = 0; g < 4; g++) {
                        mma_bf16(acc[mb][g * 2 + 0], a[mb], &b[g][0]);
                        mma_bf16(acc[mb][g * 2 + 1], a[mb], &b[g][2]);
                    }
            }
        }
    }

    // ---- epilogue ----
    const int qr = lane >> 2, qc = (lane & 3) * 2;
    float* C = br ? C1 : C0;
    __nv_bfloat16* Ch = br ? Ch1 : Ch0;
    __nv_bfloat16* Cl = br ? Cl1 : Cl0;
    #pragma unroll
    for (int mb = 0; mb < 2; mb++) {
        int rA = m0 + wm * 32 + mb * 16 + qr;
        int rB = rA + 8;
        #pragma unroll
        for (int nb = 0; nb < 8; nb++) {
            int ln = qc + wn * 64 + nb * 8;
            int col = n0 + ln;
            float vA0 = acc[mb][nb][0] + biasS[ln];
            float vA1 = acc[mb][nb][1] + biasS[ln + 1];
            float vB0 = acc[mb][nb][2] + biasS[ln];
            float vB1 = acc[mb][nb][3] + biasS[ln + 1];
            if (RELU) {
                vA0 = fmaxf(vA0, 0.f); vA1 = fmaxf(vA1, 0.f);
                vB0 = fmaxf(vB0, 0.f); vB1 = fmaxf(vB1, 0.f);
            }
            if (BF16OUT) {
                __nv_bfloat16 h0, l0, h1, l1;
                split_bf16(vA0, h0, l0); split_bf16(vA1, h1, l1);
                *reinterpret_cast<uint32_t*>(&Ch[(size_t)rA * N + col]) = pack_bf(h0, h1);
                *reinterpret_cast<uint32_t*>(&Cl[(size_t)rA * N + col]) = pack_bf(l0, l1);
                split_bf16(vB0, h0, l0); split_bf16(vB1, h1, l1);
                *reinterpret_cast<uint32_t*>(&Ch[(size_t)rB * N + col]) = pack_bf(h0, h1);
                *reinterpret_cast<uint32_t*>(&Cl[(size_t)rB * N + col]) = pack_bf(l0, l1);
            } else {
                *reinterpret_cast<float2*>(&C[(size_t)rA * N + col]) = make_float2(vA0, vA1);
                *reinterpret_cast<float2*>(&C[(size_t)rB * N + col]) = make_float2(vB0, vB1);
            }
        }
    }
}

// ================= HMMA pairwise kernel (unchanged from R3) =================
#define PBK   32
#define PSTR  80
#define POFF_HH   0
#define POFF_HL   10240
#define POFF_WH   20480
#define POFF_WL   30720
#define POFF_B    40960
#define POFF_A    50176
#define POFF_BIAS 50432
#define POFF_B2   50560
#define PSMEM     51072

__global__ __launch_bounds__(256, 2)
void pairwise_hmma_kernel(const float* __restrict__ b2v,
                          float* __restrict__ out) {
    extern __shared__ char smem[];
    const uint32_t su = smem_u32(smem);
    float* Bs    = reinterpret_cast<float*>(smem + POFF_B);
    float* As    = reinterpret_cast<float*>(smem + POFF_A);
    float* biasS = reinterpret_cast<float*>(smem + POFF_BIAS);
    float* bs2   = reinterpret_cast<float*>(smem + POFF_B2);

    const int tid  = threadIdx.x;
    const int wid  = tid >> 5;
    const int lane = tid & 31;
    const int wm   = wid >> 1;
    const int wn   = wid & 1;

    const int n0  = blockIdx.x * 128;
    const int ib2 = blockIdx.y * 2;
    const int t   = blockIdx.z;

    if (tid < 128) bs2[tid] = b2v[n0 + tid];

    const size_t arow0 = (size_t)(t * 64 + ib2) * HH;
    const size_t brow0 = (size_t)(t * 64) * HH;

    const uint32_t h_off = (uint32_t)((lane & 15) * PSTR + (lane >> 4) * 16);
    const uint32_t w_off = (uint32_t)(((lane & 7) + ((lane >> 4) << 3)) * PSTR
                                      + ((lane >> 3) & 1) * 16);

    float acc[2][8][4];
    #pragma unroll
    for (int mb = 0; mb < 2; mb++)
        #pragma unroll
        for (int nb = 0; nb < 8; nb++)
            #pragma unroll
            for (int q = 0; q < 4; q++) acc[mb][nb][q] = 0.f;

    for (int c = 0; c < 16; c++) {
        const int k0 = c * PBK;
        __syncthreads();

        if (tid < 64) {
            int r = tid >> 5, k = tid & 31;
            As[r * 32 + k] = g_A[arow0 + (size_t)r * HH + k0 + k];
        } else if (tid < 96) {
            biasS[tid - 64] = g_bias512[k0 + tid - 64];
        }
        #pragma unroll
        for (int e = 0; e < 2; e++) {
            int idx = e * 256 + tid;
            int j = idx >> 3, q = idx & 7;
            float4 v = *reinterpret_cast<const float4*>(&g_B[brow0 + (size_t)j * HH + k0 + q * 4]);
            *reinterpret_cast<float4*>(&Bs[j * 36 + q * 4]) = v;
        }
        #pragma unroll
        for (int e = 0; e < 2; e++) {
            int idx = e * 256 + tid;
            int n = idx >> 2, q = idx & 3;
            uint4 vh = *reinterpret_cast<const uint4*>(&g_W2hi[(size_t)(n0 + n) * HH + k0 + q * 8]);
            *reinterpret_cast<uint4*>(smem + POFF_WH + n * PSTR + q * 16) = vh;
            uint4 vl = *reinterpret_cast<const uint4*>(&g_W2lo[(size_t)(n0 + n) * HH + k0 + q * 8]);
            *reinterpret_cast<uint4*>(smem + POFF_WL + n * PSTR + q * 16) = vl;
        }
        __syncthreads();

        #pragma unroll
        for (int e = 0; e < 8; e++) {
            int idx = e * 256 + tid;
            int p  = idx >> 4;
            int kp = idx & 15;
            int k  = kp * 2;
            int i  = p >> 6, j = p & 63;
            float a0 = As[i * 32 + k],     a1 = As[i * 32 + k + 1];
            float b0 = Bs[j * 36 + k],     b1 = Bs[j * 36 + k + 1];
            float v0 = fmaxf(a0 - b0 + biasS[k],     0.f);
            float v1 = fmaxf(a1 - b1 + biasS[k + 1], 0.f);
            __nv_bfloat16 h0, l0, h1, l1;
            split_bf16(v0, h0, l0);
            split_bf16(v1, h1, l1);
            *reinterpret_cast<uint32_t*>(smem + POFF_HH + p * PSTR + k * 2) = pack_bf(h0, h1);
            *reinterpret_cast<uint32_t*>(smem + POFF_HL + p * PSTR + k * 2) = pack_bf(l0, l1);
        }
        __syncthreads();

        #pragma unroll
        for (int ks = 0; ks < 2; ks++) {
            #pragma unroll
            for (int term = 0; term < 3; term++) {
                const uint32_t hbase = su + (term == 2 ? POFF_HL : POFF_HH)
                                       + wm * (32 * PSTR) + ks * 32 + h_off;
                const uint32_t wbase = su + (term == 1 ? POFF_WL : POFF_WH)
                                       + wn * (64 * PSTR) + ks * 32 + w_off;
                uint32_t a[2][4], b[4][4];
                #pragma unroll
                for (int mb = 0; mb < 2; mb++)
                    ldsm4(a[mb], hbase + mb * (16 * PSTR));
                #pragma unroll
                for (int g = 0; g < 4; g++)
                    ldsm4(b[g], wbase + g * (16 * PSTR));
                #pragma unroll
                for (int mb = 0; mb < 2; mb++)
                    #pragma unroll
                    for (int g = 0; g < 4; g++) {
                        mma_bf16(acc[mb][g * 2 + 0], a[mb], &b[g][0]);
                        mma_bf16(acc[mb][g * 2 + 1], a[mb], &b[g][2]);
                    }
            }
        }
    }

    const int qr = lane >> 2, qc = (lane & 3) * 2;
    #pragma unroll
    for (int mb = 0; mb < 2; mb++) {
        int rA = wm * 32 + mb * 16 + qr;
        int rB = rA + 8;
        float* oA = out + ((size_t)(t * 64 + ib2 + (rA >> 6)) * 64 + (rA & 63)) * 256
                        + n0 + wn * 64 + qc;
        float* oB = out + ((size_t)(t * 64 + ib2 + (rB >> 6)) * 64 + (rB & 63)) * 256
                        + n0 + wn * 64 + qc;
        #pragma unroll
        for (int nb = 0; nb < 8; nb++) {
            int ln = wn * 64 + nb * 8 + qc;
            float2 vA = make_float2(acc[mb][nb][0] + bs2[ln],
                                    acc[mb][nb][1] + bs2[ln + 1]);
            float2 vB = make_float2(acc[mb][nb][2] + bs2[ln],
                                    acc[mb][nb][3] + bs2[ln + 1]);
            *reinterpret_cast<float2*>(oA + nb * 8) = vA;
            *reinterpret_cast<float2*>(oB + nb * 8) = vB;
        }
    }
}

// ---------------- host launch ----------------
extern "C" void kernel_launch(void* const* d_in, const int* in_sizes, int n_in,
                              void* d_out, int out_size) {
    const float* roi       = (const float*)d_in[0];
    const float* spatial   = (const float*)d_in[1];
    const float* subj_emb  = (const float*)d_in[3];
    const float* obj_emb   = (const float*)d_in[4];
    const float* pred_emb  = (const float*)d_in[5];
    const float* subj_w1   = (const float*)d_in[6];
    const float* subj_b1   = (const float*)d_in[7];
    const float* subj_w2   = (const float*)d_in[8];
    const float* subj_b2   = (const float*)d_in[9];
    const float* obj_w1    = (const float*)d_in[10];
    const float* obj_b1    = (const float*)d_in[11];
    const float* obj_w2    = (const float*)d_in[12];
    const float* obj_b2    = (const float*)d_in[13];
    const float* fuse_s_w1 = (const float*)d_in[14];
    const float* fuse_s_b1 = (const float*)d_in[15];
    const float* fuse_s_w2 = (const float*)d_in[16];
    const float* fuse_s_b2 = (const float*)d_in[17];
    const float* fuse_o_w1 = (const float*)d_in[18];
    const float* fuse_o_b1 = (const float*)d_in[19];
    const float* fuse_o_w2 = (const float*)d_in[20];
    const float* fuse_o_b2 = (const float*)d_in[21];
    const float* W_rs      = (const float*)d_in[22];
    const float* W_ro      = (const float*)d_in[23];
    const float* rel_w1    = (const float*)d_in[24];
    const float* rel_b1    = (const float*)d_in[25];
    const float* rel_w2    = (const float*)d_in[26];
    const float* rel_b2    = (const float*)d_in[27];
    float* out = (float*)d_out;

    // resolve scratch symbol addresses
    __nv_bfloat16 *pXh, *pXl;
    __nv_bfloat16 *pW1h_s, *pW1l_s, *pW1h_o, *pW1l_o;
    __nv_bfloat16 *pY1h_s, *pY1l_s, *pY1h_o, *pY1l_o;
    __nv_bfloat16 *pY2h_s, *pY2l_s, *pY2h_o, *pY2l_o;
    __nv_bfloat16 *pWfh_s, *pWfl_s, *pWfh_o, *pWfl_o;
    __nv_bfloat16 *pWcch_s, *pWccl_s, *pWcch_o, *pWccl_o;
    float *pA, *pB;
    float *pc_subj, *pc_obj, *pbf_s, *pbf_o, *pcv_s, *pcv_o;
    cudaGetSymbolAddress((void**)&pXh, g_Xh);
    cudaGetSymbolAddress((void**)&pXl, g_Xl);
    cudaGetSymbolAddress((void**)&pW1h_s, g_W1h_s);
    cudaGetSymbolAddress((void**)&pW1l_s, g_W1l_s);
    cudaGetSymbolAddress((void**)&pW1h_o, g_W1h_o);
    cudaGetSymbolAddress((void**)&pW1l_o, g_W1l_o);
    cudaGetSymbolAddress((void**)&pY1h_s, g_Y1h_s);
    cudaGetSymbolAddress((void**)&pY1l_s, g_Y1l_s);
    cudaGetSymbolAddress((void**)&pY1h_o, g_Y1h_o);
    cudaGetSymbolAddress((void**)&pY1l_o, g_Y1l_o);
    cudaGetSymbolAddress((void**)&pY2h_s, g_Y2h_s);
    cudaGetSymbolAddress((void**)&pY2l_s, g_Y2l_s);
    cudaGetSymbolAddress((void**)&pY2h_o, g_Y2h_o);
    cudaGetSymbolAddress((void**)&pY2l_o, g_Y2l_o);
    cudaGetSymbolAddress((void**)&pWfh_s, g_Wfh_s);
    cudaGetSymbolAddress((void**)&pWfl_s, g_Wfl_s);
    cudaGetSymbolAddress((void**)&pWfh_o, g_Wfh_o);
    cudaGetSymbolAddress((void**)&pWfl_o, g_Wfl_o);
    cudaGetSymbolAddress((void**)&pWcch_s, g_Wcch_s);
    cudaGetSymbolAddress((void**)&pWccl_s, g_Wccl_s);
    cudaGetSymbolAddress((void**)&pWcch_o, g_Wcch_o);
    cudaGetSymbolAddress((void**)&pWccl_o, g_Wccl_o);
    cudaGetSymbolAddress((void**)&pA, g_A);
    cudaGetSymbolAddress((void**)&pB, g_B);
    cudaGetSymbolAddress((void**)&pc_subj, g_c_subj);
    cudaGetSymbolAddress((void**)&pc_obj,  g_c_obj);
    cudaGetSymbolAddress((void**)&pbf_s,  g_bf_s);
    cudaGetSymbolAddress((void**)&pbf_o,  g_bf_o);
    cudaGetSymbolAddress((void**)&pcv_s,  g_cvec_s);
    cudaGetSymbolAddress((void**)&pcv_o,  g_cvec_o);

    static bool attr_set = false;
    if (!attr_set) {
        cudaFuncSetAttribute(pairwise_hmma_kernel,
                             cudaFuncAttributeMaxDynamicSharedMemorySize, PSMEM);
        attr_set = true;
    }

    // 1. pack + precompute folded weights
    pack_x_kernel<<<NROWS, 256>>>(roi, spatial);
    split_w1_kernel<<<(HH * KP1 + 255) / 256, 256>>>(subj_w1, obj_w1);
    split_w2_kernel<<<512, 256>>>(rel_w2);
    pre_vec_kernel<<<HH, 128>>>(subj_w1, subj_b1, obj_w1, obj_b1, rel_w1, rel_b1,
                                subj_emb, obj_emb, pred_emb, fuse_s_w1, fuse_o_w1);
    pre_wc_kernel<<<dim3(HH, 2), DD>>>(rel_w1, W_rs, W_ro);
    pre_wf_kernel<<<dim3(HH, 2), HH>>>(subj_w2, subj_b2, fuse_s_b1,
                                       obj_w2, obj_b2, fuse_o_b1);
    pre_wcc_kernel<<<dim3(HH, 2), HH>>>(fuse_s_w2, fuse_s_b2, fuse_o_w2, fuse_o_b2);

    dim3 cgrid(HH / 128, NROWS / 128, 2);   // (4, 32, 2)

    // 2. layer 1 (both branches): relu(X @ W1^T + c) -> Y1 hi/lo
    chain_hmma_kernel<true, true><<<cgrid, 256>>>(
        pXh, pXl, pXh, pXl, KP1,
        pW1h_s, pW1l_s, pW1h_o, pW1l_o,
        pc_subj, pc_obj,
        nullptr, nullptr,
        pY1h_s, pY1l_s, pY1h_o, pY1l_o,
        HH, KP1);

    // 3. layer 2: relu(Y1 @ Wf^T + bf) -> Y2 hi/lo
    chain_hmma_kernel<true, true><<<cgrid, 256>>>(
        pY1h_s, pY1l_s, pY1h_o, pY1l_o, HH,
        pWfh_s, pWfl_s, pWfh_o, pWfl_o,
        pbf_s, pbf_o,
        nullptr, nullptr,
        pY2h_s, pY2l_s, pY2h_o, pY2l_o,
        HH, HH);

    // 4. layer 3: Y2 @ Wcc^T + cvec -> A/B fp32
    chain_hmma_kernel<false, false><<<cgrid, 256>>>(
        pY2h_s, pY2l_s, pY2h_o, pY2l_o, HH,
        pWcch_s, pWccl_s, pWcch_o, pWccl_o,
        pcv_s, pcv_o,
        pA, pB,
        nullptr, nullptr, nullptr, nullptr,
        HH, HH);

    // 5. pairwise GEMM on tensor cores (HMMA)
    pairwise_hmma_kernel<<<dim3(2, 32, 64), 256, PSMEM>>>(rel_b2, out);

    (void)in_sizes; (void)n_in; (void)out_size;
}

// round 5
// speedup vs baseline: 2.8196x; 1.1887x over previous
#include <cuda_runtime.h>
#include <cuda_bf16.h>
#include <cstdint>
#include <cstddef>

// ---------------- problem constants ----------------
#define TT      64
#define MM      64
#define NROWS   4096      // T*M
#define ROI     2048
#define SPA     4
#define WORD    300
#define ROISPA  2052      // ROI+SPA
#define INW     2352      // ROI+SPA+WORD
#define HH      512
#define DD      256
#define RELIN   556       // D + WORD
#define KP1     2080      // ROISPA padded to 65*32

// ---------------- scratch (device globals; no allocation) ----------------
__device__ __nv_bfloat16 g_Xh[NROWS * KP1], g_Xl[NROWS * KP1];
__device__ __nv_bfloat16 g_W1h_s[HH * KP1], g_W1l_s[HH * KP1];
__device__ __nv_bfloat16 g_W1h_o[HH * KP1], g_W1l_o[HH * KP1];
__device__ __nv_bfloat16 g_Y1h_s[NROWS * HH], g_Y1l_s[NROWS * HH];
__device__ __nv_bfloat16 g_Y1h_o[NROWS * HH], g_Y1l_o[NROWS * HH];
__device__ __nv_bfloat16 g_Y2h_s[NROWS * HH], g_Y2l_s[NROWS * HH];
__device__ __nv_bfloat16 g_Y2h_o[NROWS * HH], g_Y2l_o[NROWS * HH];
__device__ __nv_bfloat16 g_Wfh_s[HH * HH], g_Wfl_s[HH * HH];
__device__ __nv_bfloat16 g_Wfh_o[HH * HH], g_Wfl_o[HH * HH];
__device__ __nv_bfloat16 g_Wcch_s[HH * HH], g_Wccl_s[HH * HH];
__device__ __nv_bfloat16 g_Wcch_o[HH * HH], g_Wccl_o[HH * HH];
__device__ float g_A[NROWS * HH];
__device__ float g_B[NROWS * HH];
__device__ float g_Wsum_s[HH * DD], g_Wsum_o[HH * DD];
__device__ float g_Wc_s  [HH * DD], g_Wc_o  [HH * DD];
__device__ float g_c_subj[HH], g_c_obj[HH], g_bias512[HH];
__device__ float g_bf_s[HH], g_bf_o[HH], g_cvec_s[HH], g_cvec_o[HH];
__device__ __nv_bfloat16 g_W2hi[DD * HH];
__device__ __nv_bfloat16 g_W2lo[DD * HH];

// ---------------- helpers ----------------
__device__ __forceinline__ uint32_t smem_u32(const void* p) {
    uint32_t a;
    asm("{ .reg .u64 t; cvta.to.shared.u64 t, %1; cvt.u32.u64 %0, t; }"
        : "=r"(a) : "l"(p));
    return a;
}
__device__ __forceinline__ void ldsm4(uint32_t* r, uint32_t addr) {
    asm volatile("ldmatrix.sync.aligned.m8n8.x4.shared.b16 {%0,%1,%2,%3}, [%4];"
        : "=r"(r[0]), "=r"(r[1]), "=r"(r[2]), "=r"(r[3]) : "r"(addr));
}
__device__ __forceinline__ void mma_bf16(float* c, const uint32_t* a, const uint32_t* b) {
    asm volatile(
        "mma.sync.aligned.m16n8k16.row.col.f32.bf16.bf16.f32 "
        "{%0,%1,%2,%3}, {%4,%5,%6,%7}, {%8,%9}, {%0,%1,%2,%3};"
        : "+f"(c[0]), "+f"(c[1]), "+f"(c[2]), "+f"(c[3])
        : "r"(a[0]), "r"(a[1]), "r"(a[2]), "r"(a[3]), "r"(b[0]), "r"(b[1]));
}
__device__ __forceinline__ void split_bf16(float v, __nv_bfloat16& h, __nv_bfloat16& l) {
    h = __float2bfloat16(v);
    l = __float2bfloat16(v - __bfloat162float(h));
}
__device__ __forceinline__ uint32_t pack_bf(__nv_bfloat16 a, __nv_bfloat16 b) {
    return ((uint32_t)__bfloat16_as_ushort(b) << 16) | __bfloat16_as_ushort(a);
}
__device__ __forceinline__ void cp16(uint32_t dst, const void* src) {
    asm volatile("cp.async.ca.shared.global [%0], [%1], 16;" :: "r"(dst), "l"(src));
}
__device__ __forceinline__ void cp_commit() {
    asm volatile("cp.async.commit_group;");
}
__device__ __forceinline__ void cp_wait0() {
    asm volatile("cp.async.wait_group 0;" ::: "memory");
}

// ---------------- pack X = [roi | spatial | 0pad] -> bf16 hi/lo ----------------
__global__ void pack_x_kernel(const float* __restrict__ roi,
                              const float* __restrict__ spa) {
    int r = blockIdx.x;
    for (int k = threadIdx.x; k < KP1; k += blockDim.x) {
        float v = 0.f;
        if (k < ROI)         v = roi[(size_t)r * ROI + k];
        else if (k < ROISPA) v = spa[(size_t)r * SPA + (k - ROI)];
        __nv_bfloat16 h, l; split_bf16(v, h, l);
        g_Xh[(size_t)r * KP1 + k] = h;
        g_Xl[(size_t)r * KP1 + k] = l;
    }
}

// ---------------- split layer-1 weights ----------------
__global__ void split_w1_kernel(const float* __restrict__ s_w1,
                                const float* __restrict__ o_w1) {
    int idx = blockIdx.x * 256 + threadIdx.x;
    if (idx >= HH * KP1) return;
    int n = idx / KP1, k = idx - n * KP1;
    float vs = (k < ROISPA) ? s_w1[(size_t)n * INW + k] : 0.f;
    float vo = (k < ROISPA) ? o_w1[(size_t)n * INW + k] : 0.f;
    __nv_bfloat16 h, l;
    split_bf16(vs, h, l); g_W1h_s[idx] = h; g_W1l_s[idx] = l;
    split_bf16(vo, h, l); g_W1h_o[idx] = h; g_W1l_o[idx] = l;
}

// ---------------- split rel_w2 ----------------
__global__ void split_w2_kernel(const float* __restrict__ w2) {
    int idx = blockIdx.x * 256 + threadIdx.x;
    float v = w2[idx];
    __nv_bfloat16 h, l; split_bf16(v, h, l);
    g_W2hi[idx] = h;
    g_W2lo[idx] = l;
}

// ---------------- constant biases + Wsum ----------------
__global__ void pre_vec_kernel(const float* __restrict__ subj_w1, const float* __restrict__ subj_b1,
                               const float* __restrict__ obj_w1,  const float* __restrict__ obj_b1,
                               const float* __restrict__ rel_w1,  const float* __restrict__ rel_b1,
                               const float* __restrict__ subj_emb, const float* __restrict__ obj_emb,
                               const float* __restrict__ pred_emb,
                               const float* __restrict__ fuse_s_w1, const float* __restrict__ fuse_o_w1) {
    int h = blockIdx.x;
    int t = threadIdx.x;
    float s1 = 0.f, s2 = 0.f, s3 = 0.f;
    for (int w = t; w < WORD; w += 128) {
        s1 += subj_w1[(size_t)h * INW + ROISPA + w] * subj_emb[w];
        s2 += obj_w1 [(size_t)h * INW + ROISPA + w] * obj_emb[w];
        s3 += rel_w1 [(size_t)h * RELIN + DD + w]   * pred_emb[w];
    }
    for (int o = 16; o > 0; o >>= 1) {
        s1 += __shfl_down_sync(0xffffffffu, s1, o);
        s2 += __shfl_down_sync(0xffffffffu, s2, o);
        s3 += __shfl_down_sync(0xffffffffu, s3, o);
    }
    __shared__ float red[3][4];
    int wrp = t >> 5, lan = t & 31;
    if (lan == 0) { red[0][wrp] = s1; red[1][wrp] = s2; red[2][wrp] = s3; }
    __syncthreads();
    if (t == 0) {
        g_c_subj[h]  = red[0][0] + red[0][1] + red[0][2] + red[0][3] + subj_b1[h];
        g_c_obj[h]   = red[1][0] + red[1][1] + red[1][2] + red[1][3] + obj_b1[h];
        g_bias512[h] = red[2][0] + red[2][1] + red[2][2] + red[2][3] + rel_b1[h];
    }
    for (int d = t; d < DD; d += 128) {
        g_Wsum_s[h * DD + d] = fuse_s_w1[(size_t)h * (2*DD) + d] + fuse_s_w1[(size_t)h * (2*DD) + DD + d];
        g_Wsum_o[h * DD + d] = fuse_o_w1[(size_t)h * (2*DD) + d] + fuse_o_w1[(size_t)h * (2*DD) + DD + d];
    }
}

// ---------------- tiled NN GEMM: C = A(MxK) @ B(KxN) ----------------
// grid (N/64, M/64, 2 branches), 256 threads, 4x4 micro.
template<bool BF16OUT>
__global__ __launch_bounds__(256)
void nn_gemm_kernel(const float* __restrict__ A0, const float* __restrict__ B0,
                    float* __restrict__ C0, __nv_bfloat16* __restrict__ Ch0, __nv_bfloat16* __restrict__ Cl0,
                    const float* __restrict__ A1, const float* __restrict__ B1,
                    float* __restrict__ C1, __nv_bfloat16* __restrict__ Ch1, __nv_bfloat16* __restrict__ Cl1,
                    int N, int K, int lda, int ldb) {
    __shared__ float Ask[16][68];
    __shared__ float Bs [16][68];
    const int br = blockIdx.z;
    const float* A = br ? A1 : A0;
    const float* B = br ? B1 : B0;
    const int m0 = blockIdx.y * 64, n0 = blockIdx.x * 64;
    const int tid = threadIdx.x;
    const int tr = tid >> 4, tc = tid & 15;
    float acc[4][4];
    #pragma unroll
    for (int i = 0; i < 4; i++)
        #pragma unroll
        for (int j = 0; j < 4; j++) acc[i][j] = 0.f;

    for (int k0 = 0; k0 < K; k0 += 16) {
        {
            int r = tid >> 2, kq = (tid & 3) * 4;
            float4 v = *reinterpret_cast<const float4*>(&A[(size_t)(m0 + r) * lda + k0 + kq]);
            Ask[kq + 0][r] = v.x; Ask[kq + 1][r] = v.y;
            Ask[kq + 2][r] = v.z; Ask[kq + 3][r] = v.w;
        }
        {
            int k = tid >> 4, nq = (tid & 15) * 4;
            float4 v = *reinterpret_cast<const float4*>(&B[(size_t)(k0 + k) * ldb + n0 + nq]);
            *reinterpret_cast<float4*>(&Bs[k][nq]) = v;
        }
        __syncthreads();
        #pragma unroll
        for (int k = 0; k < 16; k++) {
            float a[4], b[4];
            *reinterpret_cast<float4*>(a) = *reinterpret_cast<const float4*>(&Ask[k][tr * 4]);
            *reinterpret_cast<float4*>(b) = *reinterpret_cast<const float4*>(&Bs[k][tc * 4]);
            #pragma unroll
            for (int i = 0; i < 4; i++)
                #pragma unroll
                for (int j = 0; j < 4; j++)
                    acc[i][j] = fmaf(a[i], b[j], acc[i][j]);
        }
        __syncthreads();
    }

    if (BF16OUT) {
        __nv_bfloat16* Ch = br ? Ch1 : Ch0;
        __nv_bfloat16* Cl = br ? Cl1 : Cl0;
        #pragma unroll
        for (int i = 0; i < 4; i++)
            #pragma unroll
            for (int j = 0; j < 4; j++) {
                __nv_bfloat16 h, l; split_bf16(acc[i][j], h, l);
                size_t off = (size_t)(m0 + tr * 4 + i) * N + n0 + tc * 4 + j;
                Ch[off] = h; Cl[off] = l;
            }
    } else {
        float* C = br ? C1 : C0;
        #pragma unroll
        for (int i = 0; i < 4; i++)
            #pragma unroll
            for (int j = 0; j < 4; j++)
                C[(size_t)(m0 + tr * 4 + i) * N + n0 + tc * 4 + j] = acc[i][j];
    }
}

// ---------------- batched small GEMV for bias folds ----------------
// y=0: bf_s = Wsum_s@subj_b2 + fuse_s_b1 ; y=1: bf_o ; y=2: cvec_s = Wc_s@fuse_s_b2 ; y=3: cvec_o
__global__ void gemv4_kernel(const float* __restrict__ subj_b2, const float* __restrict__ obj_b2,
                             const float* __restrict__ fuse_s_b1, const float* __restrict__ fuse_o_b1,
                             const float* __restrict__ fuse_s_b2, const float* __restrict__ fuse_o_b2) {
    int which = blockIdx.y;
    const float *A, *v, *add; float* o;
    if      (which == 0) { A = g_Wsum_s; v = subj_b2;  add = fuse_s_b1; o = g_bf_s; }
    else if (which == 1) { A = g_Wsum_o; v = obj_b2;   add = fuse_o_b1; o = g_bf_o; }
    else if (which == 2) { A = g_Wc_s;   v = fuse_s_b2; add = nullptr;  o = g_cvec_s; }
    else                 { A = g_Wc_o;   v = fuse_o_b2; add = nullptr;  o = g_cvec_o; }
    int h = blockIdx.x * 8 + (threadIdx.x >> 5);
    int lane = threadIdx.x & 31;
    float s = 0.f;
    for (int d = lane; d < DD; d += 32) s += A[h * DD + d] * v[d];
    #pragma unroll
    for (int off = 16; off > 0; off >>= 1) s += __shfl_down_sync(0xffffffffu, s, off);
    if (lane == 0) o[h] = s + (add ? add[h] : 0.f);
}

// ================= chain HMMA GEMM (bf16 3-term, cp.async double-buffered) ====
#define CPSTR   80
#define CBUFSZ  40960
#define CSMEM   (512 + 2 * CBUFSZ)   // 82432

template<bool RELU, bool BF16OUT>
__global__ __launch_bounds__(256, 2)
void chain_hmma_kernel(const __nv_bfloat16* __restrict__ Xh0, const __nv_bfloat16* __restrict__ Xl0,
                       const __nv_bfloat16* __restrict__ Xh1, const __nv_bfloat16* __restrict__ Xl1,
                       int ldx,
                       const __nv_bfloat16* __restrict__ Wh0, const __nv_bfloat16* __restrict__ Wl0,
                       const __nv_bfloat16* __restrict__ Wh1, const __nv_bfloat16* __restrict__ Wl1,
                       const float* __restrict__ bias0, const float* __restrict__ bias1,
                       float* __restrict__ C0, float* __restrict__ C1,
                       __nv_bfloat16* __restrict__ Ch0, __nv_bfloat16* __restrict__ Cl0,
                       __nv_bfloat16* __restrict__ Ch1, __nv_bfloat16* __restrict__ Cl1,
                       int N, int K) {
    extern __shared__ char smem[];
    const uint32_t su = smem_u32(smem);
    float* biasS = reinterpret_cast<float*>(smem);

    const int tid  = threadIdx.x;
    const int wid  = tid >> 5;
    const int lane = tid & 31;
    const int wm   = wid >> 1;
    const int wn   = wid & 1;
    const int n0   = blockIdx.x * 128;
    const int m0   = blockIdx.y * 128;
    const int br   = blockIdx.z;

    const __nv_bfloat16* Xh = br ? Xh1 : Xh0;
    const __nv_bfloat16* Xl = br ? Xl1 : Xl0;
    const __nv_bfloat16* Wh = br ? Wh1 : Wh0;
    const __nv_bfloat16* Wl = br ? Wl1 : Wl0;
    const float* bias = br ? bias1 : bias0;

    if (tid < 128) biasS[tid] = bias[n0 + tid];

    auto stage = [&](int k0, int b) {
        uint32_t base = su + 512 + (uint32_t)b * CBUFSZ;
        #pragma unroll
        for (int e = 0; e < 2; e++) {
            int idx = e * 256 + tid;
            int r = idx >> 2, q = idx & 3;
            cp16(base +         r * CPSTR + q * 16, Xh + (size_t)(m0 + r) * ldx + k0 + q * 8);
            cp16(base + 10240 + r * CPSTR + q * 16, Xl + (size_t)(m0 + r) * ldx + k0 + q * 8);
            cp16(base + 20480 + r * CPSTR + q * 16, Wh + (size_t)(n0 + r) * K + k0 + q * 8);
            cp16(base + 30720 + r * CPSTR + q * 16, Wl + (size_t)(n0 + r) * K + k0 + q * 8);
        }
    };

    const uint32_t h_off = (uint32_t)((lane & 15) * CPSTR + (lane >> 4) * 16);
    const uint32_t w_off = (uint32_t)(((lane & 7) + ((lane >> 4) << 3)) * CPSTR
                                      + ((lane >> 3) & 1) * 16);

    float acc[2][8][4];
    #pragma unroll
    for (int mb = 0; mb < 2; mb++)
        #pragma unroll
        for (int nb = 0; nb < 8; nb++)
            #pragma unroll
            for (int q = 0; q < 4; q++) acc[mb][nb][q] = 0.f;

    stage(0, 0); cp_commit();
    const int nk = K / 32;

    for (int c = 0; c < nk; c++) {
        cp_wait0();
        __syncthreads();
        if (c + 1 < nk) { stage((c + 1) * 32, (c + 1) & 1); cp_commit(); }

        const uint32_t base = su + 512 + (uint32_t)(c & 1) * CBUFSZ;
        #pragma unroll
        for (int ks = 0; ks < 2; ks++) {
            #pragma unroll
            for (int term = 0; term < 3; term++) {
                const uint32_t hbase = base + (term == 2 ? 10240 : 0)
                                       + wm * (32 * CPSTR) + ks * 32 + h_off;
                const uint32_t wbase = base + 20480 + (term == 1 ? 10240 : 0)
                                       + wn * (64 * CPSTR) + ks * 32 + w_off;
                uint32_t a[2][4], b[4][4];
                #pragma unroll
                for (int mb = 0; mb < 2; mb++)
                    ldsm4(a[mb], hbase + mb * (16 * CPSTR));
                #pragma unroll
                for (int g = 0; g < 4; g++)
                    ldsm4(b[g], wbase + g * (16 * CPSTR));
                #pragma unroll
                for (int mb = 0; mb < 2; mb++)
                    #pragma unroll
                    for (int g = 0; g < 4; g++) {
                        mma_bf16(acc[mb][g * 2 + 0], a[mb], &b[g][0]);
                        mma_bf16(acc[mb][g * 2 + 1], a[mb], &b[g][2]);
                    }
            }
        }
    }

    // ---- epilogue ----
    const int qr = lane >> 2, qc = (lane & 3) * 2;
    float* C = br ? C1 : C0;
    __nv_bfloat16* Ch = br ? Ch1 : Ch0;
    __nv_bfloat16* Cl = br ? Cl1 : Cl0;
    #pragma unroll
    for (int mb = 0; mb < 2; mb++) {
        int rA = m0 + wm * 32 + mb * 16 + qr;
        int rB = rA + 8;
        #pragma unroll
        for (int nb = 0; nb < 8; nb++) {
            int ln = qc + wn * 64 + nb * 8;
            int col = n0 + ln;
            float vA0 = acc[mb][nb][0] + biasS[ln];
            float vA1 = acc[mb][nb][1] + biasS[ln + 1];
            float vB0 = acc[mb][nb][2] + biasS[ln];
            float vB1 = acc[mb][nb][3] + biasS[ln + 1];
            if (RELU) {
                vA0 = fmaxf(vA0, 0.f); vA1 = fmaxf(vA1, 0.f);
                vB0 = fmaxf(vB0, 0.f); vB1 = fmaxf(vB1, 0.f);
            }
            if (BF16OUT) {
                __nv_bfloat16 h0, l0, h1, l1;
                split_bf16(vA0, h0, l0); split_bf16(vA1, h1, l1);
                *reinterpret_cast<uint32_t*>(&Ch[(size_t)rA * N + col]) = pack_bf(h0, h1);
                *reinterpret_cast<uint32_t*>(&Cl[(size_t)rA * N + col]) = pack_bf(l0, l1);
                split_bf16(vB0, h0, l0); split_bf16(vB1, h1, l1);
                *reinterpret_cast<uint32_t*>(&Ch[(size_t)rB * N + col]) = pack_bf(h0, h1);
                *reinterpret_cast<uint32_t*>(&Cl[(size_t)rB * N + col]) = pack_bf(l0, l1);
            } else {
                *reinterpret_cast<float2*>(&C[(size_t)rA * N + col]) = make_float2(vA0, vA1);
                *reinterpret_cast<float2*>(&C[(size_t)rB * N + col]) = make_float2(vB0, vB1);
            }
        }
    }
}

// ================= HMMA pairwise kernel (cp.async double-buffered) =============
// smem layout:
//  0      b2        512
//  512    Hh        10240
//  10752  Hl        10240
//  20992  buf0 { bias 128 | A 256 | B 64x144=9216 | Wh 10240 | Wl 10240 } = 30080
//  51072  buf1
#define PW_HH    512
#define PW_HL    10752
#define PW_BUF0  20992
#define PW_BUFSZ 30080
#define PSTR     80
#define PSMEM    (PW_BUF0 + 2 * PW_BUFSZ)   // 81152

__global__ __launch_bounds__(256, 2)
void pairwise_hmma_kernel(const float* __restrict__ b2v,
                          float* __restrict__ out) {
    extern __shared__ char smem[];
    const uint32_t su = smem_u32(smem);
    float* bs2 = reinterpret_cast<float*>(smem);

    const int tid  = threadIdx.x;
    const int wid  = tid >> 5;
    const int lane = tid & 31;
    const int wm   = wid >> 1;
    const int wn   = wid & 1;

    const int n0  = blockIdx.x * 128;
    const int ib2 = blockIdx.y * 2;
    const int t   = blockIdx.z;

    if (tid < 128) bs2[tid] = b2v[n0 + tid];

    const size_t arow0 = (size_t)(t * 64 + ib2) * HH;
    const size_t brow0 = (size_t)(t * 64) * HH;

    auto stage = [&](int k0, int b) {
        uint32_t base = su + PW_BUF0 + (uint32_t)b * PW_BUFSZ;
        if (tid < 8) {                             // bias chunk: 32 f
            cp16(base + tid * 16, g_bias512 + k0 + tid * 4);
        } else if (tid < 24) {                     // A: 2 rows x 32 f
            int i = tid - 8, r = i >> 3, q = i & 7;
            cp16(base + 128 + r * 128 + q * 16, g_A + arow0 + (size_t)r * HH + k0 + q * 4);
        }
        #pragma unroll
        for (int e = 0; e < 2; e++) {              // B: 64 x 32 f, stride 144B
            int idx = e * 256 + tid;
            int j = idx >> 3, q = idx & 7;
            cp16(base + 384 + j * 144 + q * 16, g_B + brow0 + (size_t)j * HH + k0 + q * 4);
        }
        #pragma unroll
        for (int e = 0; e < 2; e++) {              // Wh/Wl: 128 x 32 bf16
            int idx = e * 256 + tid;
            int n = idx >> 2, q = idx & 3;
            cp16(base + 9600  + n * PSTR + q * 16, g_W2hi + (size_t)(n0 + n) * HH + k0 + q * 8);
            cp16(base + 19840 + n * PSTR + q * 16, g_W2lo + (size_t)(n0 + n) * HH + k0 + q * 8);
        }
    };

    const uint32_t h_off = (uint32_t)((lane & 15) * PSTR + (lane >> 4) * 16);
    const uint32_t w_off = (uint32_t)(((lane & 7) + ((lane >> 4) << 3)) * PSTR
                                      + ((lane >> 3) & 1) * 16);

    float acc[2][8][4];
    #pragma unroll
    for (int mb = 0; mb < 2; mb++)
        #pragma unroll
        for (int nb = 0; nb < 8; nb++)
            #pragma unroll
            for (int q = 0; q < 4; q++) acc[mb][nb][q] = 0.f;

    stage(0, 0); cp_commit();

    for (int c = 0; c < 16; c++) {
        cp_wait0();
        __syncthreads();                 // buf(c) ready; all mma(c-1) reads done
        if (c + 1 < 16) { stage((c + 1) * 32, (c + 1) & 1); cp_commit(); }

        const uint32_t base = su + PW_BUF0 + (uint32_t)(c & 1) * PW_BUFSZ;
        const float* biasB = reinterpret_cast<const float*>(smem + (base - su));
        const float* AsB   = reinterpret_cast<const float*>(smem + (base - su) + 128);
        const float* BsB   = reinterpret_cast<const float*>(smem + (base - su) + 384);

        // ---- build Hh/Hl (128 x 32 bf16) ----
        #pragma unroll
        for (int e = 0; e < 8; e++) {
            int idx = e * 256 + tid;
            int p  = idx >> 4;
            int kp = idx & 15;
            int k  = kp * 2;
            int i  = p >> 6, j = p & 63;
            float a0 = AsB[i * 32 + k],  a1 = AsB[i * 32 + k + 1];
            float b0 = BsB[j * 36 + k],  b1 = BsB[j * 36 + k + 1];
            float v0 = fmaxf(a0 - b0 + biasB[k],     0.f);
            float v1 = fmaxf(a1 - b1 + biasB[k + 1], 0.f);
            __nv_bfloat16 h0, l0, h1, l1;
            split_bf16(v0, h0, l0);
            split_bf16(v1, h1, l1);
            *reinterpret_cast<uint32_t*>(smem + PW_HH + p * PSTR + k * 2) = pack_bf(h0, h1);
            *reinterpret_cast<uint32_t*>(smem + PW_HL + p * PSTR + k * 2) = pack_bf(l0, l1);
        }
        __syncthreads();                 // H staged

        #pragma unroll
        for (int ks = 0; ks < 2; ks++) {
            #pragma unroll
            for (int term = 0; term < 3; term++) {
                const uint32_t hbase = su + (term == 2 ? PW_HL : PW_HH)
                                       + wm * (32 * PSTR) + ks * 32 + h_off;
                const uint32_t wbase = base + 9600 + (term == 1 ? 10240 : 0)
                                       + wn * (64 * PSTR) + ks * 32 + w_off;
                uint32_t a[2][4], b[4][4];
                #pragma unroll
                for (int mb = 0; mb < 2; mb++)
                    ldsm4(a[mb], hbase + mb * (16 * PSTR));
                #pragma unroll
                for (int g = 0; g < 4; g++)
                    ldsm4(b[g], wbase + g * (16 * PSTR));
                #pragma unroll
                for (int mb = 0; mb < 2; mb++)
                    #pragma unroll
                    for (int g = 0; g < 4; g++) {
                        mma_bf16(acc[mb][g * 2 + 0], a[mb], &b[g][0]);
                        mma_bf16(acc[mb][g * 2 + 1], a[mb], &b[g][2]);
                    }
            }
        }
    }

    const int qr = lane >> 2, qc = (lane & 3) * 2;
    #pragma unroll
    for (int mb = 0; mb < 2; mb++) {
        int rA = wm * 32 + mb * 16 + qr;
        int rB = rA + 8;
        float* oA = out + ((size_t)(t * 64 + ib2 + (rA >> 6)) * 64 + (rA & 63)) * 256
                        + n0 + wn * 64 + qc;
        float* oB = out + ((size_t)(t * 64 + ib2 + (rB >> 6)) * 64 + (rB & 63)) * 256
                        + n0 + wn * 64 + qc;
        #pragma unroll
        for (int nb = 0; nb < 8; nb++) {
            int ln = wn * 64 + nb * 8 + qc;
            float2 vA = make_float2(acc[mb][nb][0] + bs2[ln],
                                    acc[mb][nb][1] + bs2[ln + 1]);
            float2 vB = make_float2(acc[mb][nb][2] + bs2[ln],
                                    acc[mb][nb][3] + bs2[ln + 1]);
            *reinterpret_cast<float2*>(oA + nb * 8) = vA;
            *reinterpret_cast<float2*>(oB + nb * 8) = vB;
        }
    }
}

// ---------------- host launch ----------------
extern "C" void kernel_launch(void* const* d_in, const int* in_sizes, int n_in,
                              void* d_out, int out_size) {
    const float* roi       = (const float*)d_in[0];
    const float* spatial   = (const float*)d_in[1];
    const float* subj_emb  = (const float*)d_in[3];
    const float* obj_emb   = (const float*)d_in[4];
    const float* pred_emb  = (const float*)d_in[5];
    const float* subj_w1   = (const float*)d_in[6];
    const float* subj_b1   = (const float*)d_in[7];
    const float* subj_w2   = (const float*)d_in[8];
    const float* subj_b2   = (const float*)d_in[9];
    const float* obj_w1    = (const float*)d_in[10];
    const float* obj_b1    = (const float*)d_in[11];
    const float* obj_w2    = (const float*)d_in[12];
    const float* obj_b2    = (const float*)d_in[13];
    const float* fuse_s_w1 = (const float*)d_in[14];
    const float* fuse_s_b1 = (const float*)d_in[15];
    const float* fuse_s_w2 = (const float*)d_in[16];
    const float* fuse_s_b2 = (const float*)d_in[17];
    const float* fuse_o_w1 = (const float*)d_in[18];
    const float* fuse_o_b1 = (const float*)d_in[19];
    const float* fuse_o_w2 = (const float*)d_in[20];
    const float* fuse_o_b2 = (const float*)d_in[21];
    const float* W_rs      = (const float*)d_in[22];
    const float* W_ro      = (const float*)d_in[23];
    const float* rel_w1    = (const float*)d_in[24];
    const float* rel_b1    = (const float*)d_in[25];
    const float* rel_w2    = (const float*)d_in[26];
    const float* rel_b2    = (const float*)d_in[27];
    float* out = (float*)d_out;

    __nv_bfloat16 *pXh, *pXl;
    __nv_bfloat16 *pW1h_s, *pW1l_s, *pW1h_o, *pW1l_o;
    __nv_bfloat16 *pY1h_s, *pY1l_s, *pY1h_o, *pY1l_o;
    __nv_bfloat16 *pY2h_s, *pY2l_s, *pY2h_o, *pY2l_o;
    __nv_bfloat16 *pWfh_s, *pWfl_s, *pWfh_o, *pWfl_o;
    __nv_bfloat16 *pWcch_s, *pWccl_s, *pWcch_o, *pWccl_o;
    float *pA, *pB, *pWsum_s, *pWsum_o, *pWc_s, *pWc_o;
    float *pc_subj, *pc_obj, *pbf_s, *pbf_o, *pcv_s, *pcv_o;
    cudaGetSymbolAddress((void**)&pXh, g_Xh);
    cudaGetSymbolAddress((void**)&pXl, g_Xl);
    cudaGetSymbolAddress((void**)&pW1h_s, g_W1h_s);
    cudaGetSymbolAddress((void**)&pW1l_s, g_W1l_s);
    cudaGetSymbolAddress((void**)&pW1h_o, g_W1h_o);
    cudaGetSymbolAddress((void**)&pW1l_o, g_W1l_o);
    cudaGetSymbolAddress((void**)&pY1h_s, g_Y1h_s);
    cudaGetSymbolAddress((void**)&pY1l_s, g_Y1l_s);
    cudaGetSymbolAddress((void**)&pY1h_o, g_Y1h_o);
    cudaGetSymbolAddress((void**)&pY1l_o, g_Y1l_o);
    cudaGetSymbolAddress((void**)&pY2h_s, g_Y2h_s);
    cudaGetSymbolAddress((void**)&pY2l_s, g_Y2l_s);
    cudaGetSymbolAddress((void**)&pY2h_o, g_Y2h_o);
    cudaGetSymbolAddress((void**)&pY2l_o, g_Y2l_o);
    cudaGetSymbolAddress((void**)&pWfh_s, g_Wfh_s);
    cudaGetSymbolAddress((void**)&pWfl_s, g_Wfl_s);
    cudaGetSymbolAddress((void**)&pWfh_o, g_Wfh_o);
    cudaGetSymbolAddress((void**)&pWfl_o, g_Wfl_o);
    cudaGetSymbolAddress((void**)&pWcch_s, g_Wcch_s);
    cudaGetSymbolAddress((void**)&pWccl_s, g_Wccl_s);
    cudaGetSymbolAddress((void**)&pWcch_o, g_Wcch_o);
    cudaGetSymbolAddress((void**)&pWccl_o, g_Wccl_o);
    cudaGetSymbolAddress((void**)&pA, g_A);
    cudaGetSymbolAddress((void**)&pB, g_B);
    cudaGetSymbolAddress((void**)&pWsum_s, g_Wsum_s);
    cudaGetSymbolAddress((void**)&pWsum_o, g_Wsum_o);
    cudaGetSymbolAddress((void**)&pWc_s, g_Wc_s);
    cudaGetSymbolAddress((void**)&pWc_o, g_Wc_o);
    cudaGetSymbolAddress((void**)&pc_subj, g_c_subj);
    cudaGetSymbolAddress((void**)&pc_obj,  g_c_obj);
    cudaGetSymbolAddress((void**)&pbf_s,  g_bf_s);
    cudaGetSymbolAddress((void**)&pbf_o,  g_bf_o);
    cudaGetSymbolAddress((void**)&pcv_s,  g_cvec_s);
    cudaGetSymbolAddress((void**)&pcv_o,  g_cvec_o);

    static bool attr_set = false;
    if (!attr_set) {
        cudaFuncSetAttribute(pairwise_hmma_kernel,
                             cudaFuncAttributeMaxDynamicSharedMemorySize, PSMEM);
        cudaFuncSetAttribute(chain_hmma_kernel<true, true>,
                             cudaFuncAttributeMaxDynamicSharedMemorySize, CSMEM);
        cudaFuncSetAttribute(chain_hmma_kernel<false, false>,
                             cudaFuncAttributeMaxDynamicSharedMemorySize, CSMEM);
        attr_set = true;
    }

    // 1. pack + precompute
    pack_x_kernel<<<NROWS, 256>>>(roi, spatial);
    split_w1_kernel<<<(HH * KP1 + 255) / 256, 256>>>(subj_w1, obj_w1);
    split_w2_kernel<<<512, 256>>>(rel_w2);
    pre_vec_kernel<<<HH, 128>>>(subj_w1, subj_b1, obj_w1, obj_b1, rel_w1, rel_b1,
                                subj_emb, obj_emb, pred_emb, fuse_s_w1, fuse_o_w1);
    // Wc = rel_w1[:, :256] @ Wr   (M=512, N=256, K=256)
    nn_gemm_kernel<false><<<dim3(4, 8, 2), 256>>>(
        rel_w1, W_rs, pWc_s, nullptr, nullptr,
        rel_w1, W_ro, pWc_o, nullptr, nullptr,
        DD, DD, RELIN, DD);
    // Wf = Wsum @ w2  (M=512, N=512, K=256), bf16 split out
    nn_gemm_kernel<true><<<dim3(8, 8, 2), 256>>>(
        pWsum_s, subj_w2, nullptr, pWfh_s, pWfl_s,
        pWsum_o, obj_w2,  nullptr, pWfh_o, pWfl_o,
        HH, DD, DD, HH);
    // Wcc = Wc @ fw2  (M=512, N=512, K=256), bf16 split out
    nn_gemm_kernel<true><<<dim3(8, 8, 2), 256>>>(
        pWc_s, fuse_s_w2, nullptr, pWcch_s, pWccl_s,
        pWc_o, fuse_o_w2, nullptr, pWcch_o, pWccl_o,
        HH, DD, DD, HH);
    // bias folds
    gemv4_kernel<<<dim3(64, 4), 256>>>(subj_b2, obj_b2, fuse_s_b1, fuse_o_b1,
                                       fuse_s_b2, fuse_o_b2);

    dim3 cgrid(HH / 128, NROWS / 128, 2);

    // 2. layer 1: relu(X @ W1^T + c) -> Y1 hi/lo
    chain_hmma_kernel<true, true><<<cgrid, 256, CSMEM>>>(
        pXh, pXl, pXh, pXl, KP1,
        pW1h_s, pW1l_s, pW1h_o, pW1l_o,
        pc_subj, pc_obj,
        nullptr, nullptr,
        pY1h_s, pY1l_s, pY1h_o, pY1l_o,
        HH, KP1);

    // 3. layer 2: relu(Y1 @ Wf^T + bf) -> Y2 hi/lo
    chain_hmma_kernel<true, true><<<cgrid, 256, CSMEM>>>(
        pY1h_s, pY1l_s, pY1h_o, pY1l_o, HH,
        pWfh_s, pWfl_s, pWfh_o, pWfl_o,
        pbf_s, pbf_o,
        nullptr, nullptr,
        pY2h_s, pY2l_s, pY2h_o, pY2l_o,
        HH, HH);

    // 4. layer 3: Y2 @ Wcc^T + cvec -> A/B fp32
    chain_hmma_kernel<false, false><<<cgrid, 256, CSMEM>>>(
        pY2h_s, pY2l_s, pY2h_o, pY2l_o, HH,
        pWcch_s, pWccl_s, pWcch_o, pWccl_o,
        pcv_s, pcv_o,
        pA, pB,
        nullptr, nullptr, nullptr, nullptr,
        HH, HH);

    // 5. pairwise GEMM (HMMA, pipelined)
    pairwise_hmma_kernel<<<dim3(2, 32, 64), 256, PSMEM>>>(rel_b2, out);

    (void)in_sizes; (void)n_in; (void)out_size;
}